// round 1
// baseline (speedup 1.0000x reference)
#include <cuda_runtime.h>
#include <cuda_bf16.h>
#include <math.h>

// ---------------------------------------------------------------------------
// Problem constants
// ---------------------------------------------------------------------------
#define NSYM   100000
#define PADID  100000
#define DDIM   128     // D
#define DM     256     // 2*D
#define HID    512
#define B      4096
#define FEW    5
#define MAXK   50
#define KNEI   10
#define EPS    1e-8f
#define LNEPS  1e-5f

// ---------------------------------------------------------------------------
// Scratch (device globals -- no allocations allowed)
// ---------------------------------------------------------------------------
__device__ __align__(128) float g_P[(NSYM + 1) * 256];     // [PR | PE] per symbol
__device__ __align__(128) float g_Wt[256 * 128];           // rearranged gcn W
__device__ __align__(128) float g_qvec[B * 256];
__device__ __align__(128) float g_svec[FEW * 256];
__device__ __align__(128) float g_sg[256];                 // support_g
__device__ __align__(128) float g_sgn[1];                  // sqrt(|sg|^2+eps)
__device__ __align__(128) float g_H1[B * 512];
__device__ __align__(128) float g_tmp[B * 256];
__device__ __align__(128) float g_X[B * 256];              // query_enc
__device__ __align__(128) float g_Wihp[1024 * 256];
__device__ __align__(128) float g_WhhLp[1024 * 256];
__device__ __align__(128) float g_bsum[1024];
__device__ __align__(128) float g_whhr[1024];
__device__ __align__(128) float g_Gq[B * 1024];
__device__ __align__(128) float g_gates[B * 1024];
__device__ __align__(128) float g_c[B * 256];
__device__ __align__(128) float g_h[B * 256];

__device__ __forceinline__ float sigf(float x) { return 1.f / (1.f + expf(-x)); }

// ---------------------------------------------------------------------------
// Generic SGEMM: C[M,N] = A[M,K] @ B[N,K]^T (+bias[n]) (+res[m,n]) (relu?)
// BM=BN=128, BK=8, 256 threads, 8x8 per thread. N, K multiples of 8/128 per use.
// ---------------------------------------------------------------------------
__global__ void sgemm_kernel(const float* __restrict__ A, int lda,
                             const float* __restrict__ Bm, int ldb,
                             float* __restrict__ C, int ldc,
                             int M, int N, int K,
                             const float* __restrict__ bias,
                             const float* __restrict__ res, int ldres,
                             int relu)
{
    __shared__ __align__(16) float As[8][132];
    __shared__ __align__(16) float Bs[8][132];
    const int tid = threadIdx.x;
    const int bm = blockIdx.y * 128;
    const int bn = blockIdx.x * 128;
    const int ldr = tid >> 1;          // 0..127
    const int ldk = (tid & 1) * 4;     // 0 or 4
    const int ty  = tid >> 4;          // 0..15
    const int tx  = tid & 15;          // 0..15

    float acc[8][8];
#pragma unroll
    for (int i = 0; i < 8; i++)
#pragma unroll
        for (int j = 0; j < 8; j++) acc[i][j] = 0.f;

    const int grA = bm + ldr;
    const bool avalid = (grA < M);
    const float* Aptr = A + (size_t)grA * lda + ldk;
    const float* Bptr = Bm + (size_t)(bn + ldr) * ldb + ldk;

    for (int k0 = 0; k0 < K; k0 += 8) {
        float4 av = avalid ? *(const float4*)(Aptr + k0) : make_float4(0.f, 0.f, 0.f, 0.f);
        float4 bv = *(const float4*)(Bptr + k0);
        As[ldk + 0][ldr] = av.x; As[ldk + 1][ldr] = av.y;
        As[ldk + 2][ldr] = av.z; As[ldk + 3][ldr] = av.w;
        Bs[ldk + 0][ldr] = bv.x; Bs[ldk + 1][ldr] = bv.y;
        Bs[ldk + 2][ldr] = bv.z; Bs[ldk + 3][ldr] = bv.w;
        __syncthreads();
#pragma unroll
        for (int k = 0; k < 8; k++) {
            float a[8], b[8];
            *(float4*)&a[0] = *(const float4*)&As[k][ty * 8];
            *(float4*)&a[4] = *(const float4*)&As[k][ty * 8 + 4];
            *(float4*)&b[0] = *(const float4*)&Bs[k][tx * 8];
            *(float4*)&b[4] = *(const float4*)&Bs[k][tx * 8 + 4];
#pragma unroll
            for (int i = 0; i < 8; i++)
#pragma unroll
                for (int j = 0; j < 8; j++)
                    acc[i][j] = fmaf(a[i], b[j], acc[i][j]);
        }
        __syncthreads();
    }

#pragma unroll
    for (int i = 0; i < 8; i++) {
        int r = bm + ty * 8 + i;
        if (r < M) {
            float* crow = C + (size_t)r * ldc + bn + tx * 8;
            const float* rrow = res ? (res + (size_t)r * ldres + bn + tx * 8) : nullptr;
#pragma unroll
            for (int j = 0; j < 8; j++) {
                float v = acc[i][j];
                if (bias) v += bias[bn + tx * 8 + j];
                if (rrow) v += rrow[j];
                if (relu) v = fmaxf(v, 0.f);
                crow[j] = v;
            }
        }
    }
}

// ---------------------------------------------------------------------------
// Rearrange gcn_w_W (128 x 256) into Wt (256 x 128):
//   Wt[n][k] = W[n&127][ (n>=128 ? 128 : 0) + k ]
// so P = sym_emb @ Wt^T gives [PR | PE].
// ---------------------------------------------------------------------------
__global__ void pack_wt_kernel(const float* __restrict__ W)
{
    int n = blockIdx.x, k = threadIdx.x;
    g_Wt[n * 128 + k] = W[(n & 127) * 256 + ((n >> 7) << 7) + k];
}

// ---------------------------------------------------------------------------
// Neighbor encoder: one block (128 thr) per entity. 8202 entities:
//   [0,4096)    q_l1 / query[:,0] -> g_qvec[:, 0:128]
//   [4096,8192) q_r1 / query[:,1] -> g_qvec[:,128:256]
//   [8192,8197) s_l1 / support[:,0] -> g_svec[:, 0:128]
//   [8197,8202) s_r1 / support[:,1] -> g_svec[:,128:256]
// ---------------------------------------------------------------------------
__global__ void neighbor_kernel(const int* __restrict__ query,
                                const int* __restrict__ support,
                                const int* __restrict__ q_l1, const int* __restrict__ q_deg_l,
                                const int* __restrict__ q_r1, const int* __restrict__ q_deg_r,
                                const int* __restrict__ s_l1, const int* __restrict__ s_deg_l,
                                const int* __restrict__ s_r1, const int* __restrict__ s_deg_r,
                                const float* __restrict__ sym,
                                const float* __restrict__ gwb, const float* __restrict__ gb,
                                const float* __restrict__ gate_w,
                                const float* __restrict__ gate_temp)
{
    __shared__ float s_self[128], s_bias[128];
    __shared__ float s_proj[MAXK][128];
    __shared__ float s_cos[MAXK];
    __shared__ float s_gw[MAXK];
    __shared__ int   s_sel[KNEI];
    __shared__ float s_scal[2];   // [0]=n_self, [1]=gate

    int e = blockIdx.x;
    const int* conn; int sid, deg; float* outp;
    if (e < 4096)      { conn = q_l1 + e * 100;                sid = query[e * 2];           deg = q_deg_l[e];      outp = g_qvec + e * 256; }
    else if (e < 8192) { int i = e - 4096; conn = q_r1 + i * 100; sid = query[i * 2 + 1];   deg = q_deg_r[i];      outp = g_qvec + i * 256 + 128; }
    else if (e < 8197) { int i = e - 8192; conn = s_l1 + i * 100; sid = support[i * 2];     deg = s_deg_l[i];      outp = g_svec + i * 256; }
    else               { int i = e - 8197; conn = s_r1 + i * 100; sid = support[i * 2 + 1]; deg = s_deg_r[i];      outp = g_svec + i * 256 + 128; }

    int t = threadIdx.x, lane = t & 31, w = t >> 5;
    s_self[t] = sym[(size_t)sid * 128 + t];
    s_bias[t] = gwb[t] + gb[t];
    if (t < MAXK) { int r = conn[2 * t]; s_gw[t] = gate_w[(r == PADID) ? 0 : r]; }
    __syncthreads();

    if (w == 0) {
        float ss = 0.f;
#pragma unroll
        for (int i = 0; i < 4; i++) { float v = s_self[lane + 32 * i]; ss += v * v; }
        for (int o = 16; o > 0; o >>= 1) ss += __shfl_xor_sync(~0u, ss, o);
        if (lane == 0) s_scal[0] = sqrtf(ss + EPS);
    }
    __syncthreads();
    float nself = s_scal[0];

    for (int base = 0; base < 52; base += 4) {
        int n = base + w;
        if (n < MAXK) {
            int rel = conn[2 * n], ent = conn[2 * n + 1];
            const float* pr = g_P + (size_t)rel * 256;
            const float* pe = g_P + (size_t)ent * 256 + 128;
            float dp = 0.f, nn = 0.f;
#pragma unroll
            for (int i = 0; i < 4; i++) {
                int d = lane + 32 * i;
                float v = pr[d] + pe[d] + s_bias[d];
                v = (v > 0.f) ? v : 0.01f * v;
                if (rel == PADID) v = 0.f;
                s_proj[n][d] = v;
                dp += s_self[d] * v;
                nn += v * v;
            }
            for (int o = 16; o > 0; o >>= 1) {
                dp += __shfl_xor_sync(~0u, dp, o);
                nn += __shfl_xor_sync(~0u, nn, o);
            }
            if (lane == 0) {
                float nnei = sqrtf(nn + EPS);
                s_cos[n] = dp / (nself * nnei + EPS);
            }
        }
    }
    __syncthreads();

    if (t == 0) {
        unsigned long long used = 0ULL;
        for (int k = 0; k < KNEI; k++) {
            float best = -3.0e38f; int bi = 0;
            for (int i = 0; i < MAXK; i++) {
                if (!((used >> i) & 1ULL) && s_cos[i] > best) { best = s_cos[i]; bi = i; }
            }
            used |= 1ULL << bi;
            s_sel[k] = bi;
        }
        float gs = 0.f;
        for (int i = 0; i < MAXK; i++) gs += s_gw[i];
        gs = (gs / 50.f) / gate_temp[0];
        float gate = sigf(gs);
        if (deg <= 0) gate = 1.f;
        s_scal[1] = gate;
    }
    __syncthreads();

    float agg = 0.f;
#pragma unroll
    for (int k = 0; k < KNEI; k++) agg += s_proj[s_sel[k]][t];
    agg /= 10.f;
    outp[t] = tanhf(s_self[t] + s_scal[1] * agg);
}

// ---------------------------------------------------------------------------
// Support encoder (5 rows) + mean -> g_sg, ||sg|| -> g_sgn. One block, 512 thr.
// ---------------------------------------------------------------------------
__global__ void support_enc_kernel(const float* __restrict__ W1, const float* __restrict__ b1,
                                   const float* __restrict__ W2, const float* __restrict__ b2,
                                   const float* __restrict__ g,  const float* __restrict__ b)
{
    __shared__ float sx[FEW][256];
    __shared__ float sh1[FEW][512];
    __shared__ float sh[FEW][256];
    __shared__ float smu[FEW], srs[FEW];
    __shared__ float ssg[256];
    int t = threadIdx.x;
    for (int i = t; i < FEW * 256; i += 512) sx[i / 256][i % 256] = g_svec[i];
    __syncthreads();
    {   // h1 = relu(x @ W1^T + b1), thread t = column j (512)
        int j = t;
        for (int r = 0; r < FEW; r++) {
            float acc = b1[j];
            for (int k = 0; k < 256; k++) acc = fmaf(sx[r][k], W1[j * 256 + k], acc);
            sh1[r][j] = fmaxf(acc, 0.f);
        }
    }
    __syncthreads();
    if (t < 256) {
        int kc = t;
        for (int r = 0; r < FEW; r++) {
            float acc = b2[kc] + sx[r][kc];
            for (int k = 0; k < 512; k++) acc = fmaf(sh1[r][k], W2[kc * 512 + k], acc);
            sh[r][kc] = acc;
        }
    }
    __syncthreads();
    if (t < FEW) {
        float mu = 0.f;
        for (int k = 0; k < 256; k++) mu += sh[t][k];
        mu /= 256.f;
        float var = 0.f;
        for (int k = 0; k < 256; k++) { float d = sh[t][k] - mu; var += d * d; }
        var /= 256.f;
        smu[t] = mu; srs[t] = 1.f / sqrtf(var + LNEPS);
    }
    __syncthreads();
    if (t < 256) {
        float acc = 0.f;
        for (int r = 0; r < FEW; r++) acc += g[t] * (sh[r][t] - smu[r]) * srs[r] + b[t];
        acc /= 5.f;
        g_sg[t] = acc;
        ssg[t] = acc;
    }
    __syncthreads();
    if (t == 0) {
        float s = 0.f;
        for (int k = 0; k < 256; k++) s += ssg[k] * ssg[k];
        g_sgn[0] = sqrtf(s + EPS);
    }
}

// ---------------------------------------------------------------------------
// LSTM prep: pack the 1024 live gate rows of Wih / Whh[:, :256], plus
// bias sum and constant r-contribution  whhr[j] = dot(sg, Whh[jm, 256:512]).
// Packed groups: [i|f|g|o] x 256, source row jm = grp*512 + within.
// ---------------------------------------------------------------------------
__global__ void prep_lstm_kernel(const float* __restrict__ Wih, const float* __restrict__ Whh,
                                 const float* __restrict__ bih, const float* __restrict__ bhh)
{
    int j = blockIdx.x;                 // 0..1023
    int grp = j >> 8, within = j & 255;
    int jm = grp * 512 + within;
    int t = threadIdx.x;                // 256
    g_Wihp[j * 256 + t]  = Wih[jm * 256 + t];
    g_WhhLp[j * 256 + t] = Whh[jm * 512 + t];
    float p = g_sg[t] * Whh[jm * 512 + 256 + t];
    __shared__ float red[8];
    for (int o = 16; o > 0; o >>= 1) p += __shfl_xor_sync(~0u, p, o);
    if ((t & 31) == 0) red[t >> 5] = p;
    __syncthreads();
    if (t == 0) {
        float s = 0.f;
        for (int i = 0; i < 8; i++) s += red[i];
        g_whhr[j] = s;
        g_bsum[j] = bih[jm] + bhh[jm];
    }
}

// ---------------------------------------------------------------------------
// LayerNorm rows of g_tmp -> g_X (4096 rows x 256)
// ---------------------------------------------------------------------------
__global__ void ln_kernel(const float* __restrict__ g, const float* __restrict__ b)
{
    int row = blockIdx.x, t = threadIdx.x;
    float v = g_tmp[(size_t)row * 256 + t];
    __shared__ float red[8];
    __shared__ float s_mu, s_rs;
    float s = v;
    for (int o = 16; o > 0; o >>= 1) s += __shfl_xor_sync(~0u, s, o);
    if ((t & 31) == 0) red[t >> 5] = s;
    __syncthreads();
    if (t == 0) { float m = 0.f; for (int i = 0; i < 8; i++) m += red[i]; s_mu = m / 256.f; }
    __syncthreads();
    float d = v - s_mu;
    float q = d * d;
    for (int o = 16; o > 0; o >>= 1) q += __shfl_xor_sync(~0u, q, o);
    if ((t & 31) == 0) red[t >> 5] = q;
    __syncthreads();
    if (t == 0) { float m = 0.f; for (int i = 0; i < 8; i++) m += red[i]; s_rs = 1.f / sqrtf(m / 256.f + LNEPS); }
    __syncthreads();
    g_X[(size_t)row * 256 + t] = g[t] * d * s_rs + b[t];
}

// ---------------------------------------------------------------------------
// LSTM elementwise step. gates packed [i|f|g|o] x 256.
// ---------------------------------------------------------------------------
__global__ void lstm_elem_kernel(const float* __restrict__ gates, int first)
{
    int row = blockIdx.x, t = threadIdx.x;
    const float* gr = gates + (size_t)row * 1024;
    float gi = gr[t], gf = gr[256 + t], gg = gr[512 + t], go = gr[768 + t];
    float c = first ? 0.f : g_c[(size_t)row * 256 + t];
    c = sigf(gf) * c + sigf(gi) * tanhf(gg);
    g_c[(size_t)row * 256 + t] = c;
    g_h[(size_t)row * 256 + t] = g_X[(size_t)row * 256 + t] + sigf(go) * tanhf(c);
}

// ---------------------------------------------------------------------------
// Final cosine vs support_g. 8 warps per block -> 8 rows, grid 512.
// ---------------------------------------------------------------------------
__global__ void final_kernel(float* __restrict__ out)
{
    __shared__ float ssg[256];
    int t = threadIdx.x, lane = t & 31, w = t >> 5;
    ssg[t] = g_sg[t];
    __syncthreads();
    int row = blockIdx.x * 8 + w;
    const float* h = g_h + (size_t)row * 256;
    float dp = 0.f, nq = 0.f;
#pragma unroll
    for (int i = 0; i < 8; i++) {
        int d = lane + 32 * i;
        float v = h[d];
        dp += v * ssg[d];
        nq += v * v;
    }
    for (int o = 16; o > 0; o >>= 1) {
        dp += __shfl_xor_sync(~0u, dp, o);
        nq += __shfl_xor_sync(~0u, nq, o);
    }
    if (lane == 0) out[row] = dp / (sqrtf(nq + EPS) * g_sgn[0]);
}

// ---------------------------------------------------------------------------
// kernel_launch
// ---------------------------------------------------------------------------
extern "C" void kernel_launch(void* const* d_in, const int* in_sizes, int n_in,
                              void* d_out, int out_size)
{
    const int*   query     = (const int*)d_in[0];
    const int*   support   = (const int*)d_in[1];
    const int*   q_l1      = (const int*)d_in[2];
    const int*   q_deg_l   = (const int*)d_in[3];
    const int*   q_r1      = (const int*)d_in[4];
    const int*   q_deg_r   = (const int*)d_in[5];
    const int*   s_l1      = (const int*)d_in[6];
    const int*   s_deg_l   = (const int*)d_in[7];
    const int*   s_r1      = (const int*)d_in[8];
    const int*   s_deg_r   = (const int*)d_in[9];
    const float* sym       = (const float*)d_in[10];
    const float* gcn_w_W   = (const float*)d_in[11];
    const float* gcn_w_b   = (const float*)d_in[12];
    const float* gcn_b     = (const float*)d_in[13];
    const float* gate_w    = (const float*)d_in[14];
    const float* gate_temp = (const float*)d_in[15];
    const float* se_W1     = (const float*)d_in[16];
    const float* se_b1     = (const float*)d_in[17];
    const float* se_W2     = (const float*)d_in[18];
    const float* se_b2     = (const float*)d_in[19];
    const float* ln_g      = (const float*)d_in[20];
    const float* ln_b      = (const float*)d_in[21];
    const float* lstm_Wih  = (const float*)d_in[22];
    const float* lstm_Whh  = (const float*)d_in[23];
    const float* lstm_bih  = (const float*)d_in[24];
    const float* lstm_bhh  = (const float*)d_in[25];
    float* out = (float*)d_out;

    // device-global scratch addresses
    float *pP, *pWt, *pQv, *pH1, *pTmp, *pX, *pWihp, *pWhhLp, *pBsum, *pWhhr, *pGq, *pGates, *pH;
    cudaGetSymbolAddress((void**)&pP,     g_P);
    cudaGetSymbolAddress((void**)&pWt,    g_Wt);
    cudaGetSymbolAddress((void**)&pQv,    g_qvec);
    cudaGetSymbolAddress((void**)&pH1,    g_H1);
    cudaGetSymbolAddress((void**)&pTmp,   g_tmp);
    cudaGetSymbolAddress((void**)&pX,     g_X);
    cudaGetSymbolAddress((void**)&pWihp,  g_Wihp);
    cudaGetSymbolAddress((void**)&pWhhLp, g_WhhLp);
    cudaGetSymbolAddress((void**)&pBsum,  g_bsum);
    cudaGetSymbolAddress((void**)&pWhhr,  g_whhr);
    cudaGetSymbolAddress((void**)&pGq,    g_Gq);
    cudaGetSymbolAddress((void**)&pGates, g_gates);
    cudaGetSymbolAddress((void**)&pH,     g_h);

    // 1) rearrange gcn weight, then P = sym_emb @ Wt^T   (100001 x 256, K=128)
    pack_wt_kernel<<<256, 128>>>(gcn_w_W);
    sgemm_kernel<<<dim3(2, (NSYM + 1 + 127) / 128), 256>>>(
        sym, 128, pWt, 128, pP, 256, NSYM + 1, 256, 128, nullptr, nullptr, 0, 0);

    // 2) neighbor encoder -> g_qvec (4096x256), g_svec (5x256)
    neighbor_kernel<<<8202, 128>>>(query, support, q_l1, q_deg_l, q_r1, q_deg_r,
                                   s_l1, s_deg_l, s_r1, s_deg_r,
                                   sym, gcn_w_b, gcn_b, gate_w, gate_temp);

    // 3) support encoder -> g_sg, g_sgn
    support_enc_kernel<<<1, 512>>>(se_W1, se_b1, se_W2, se_b2, ln_g, ln_b);

    // 4) LSTM weight packing + constants (needs g_sg)
    prep_lstm_kernel<<<1024, 256>>>(lstm_Wih, lstm_Whh, lstm_bih, lstm_bhh);

    // 5) query support-encoder: H1 = relu(qvec@W1^T+b1); tmp = H1@W2^T+b2+qvec; LN -> X
    sgemm_kernel<<<dim3(4, 32), 256>>>(pQv, 256, se_W1, 256, pH1, 512,
                                       B, 512, 256, se_b1, nullptr, 0, 1);
    sgemm_kernel<<<dim3(2, 32), 256>>>(pH1, 512, se_W2, 512, pTmp, 256,
                                       B, 256, 512, se_b2, pQv, 256, 0);
    ln_kernel<<<B, 256>>>(ln_g, ln_b);

    // 6) Gq = X @ Wihp^T + (bih+bhh)   (4096 x 1024, K=256)
    sgemm_kernel<<<dim3(8, 32), 256>>>(pX, 256, pWihp, 256, pGq, 1024,
                                       B, 1024, 256, pBsum, nullptr, 0, 0);

    // 7) LSTM steps. Step 0: gates = Gq (h_r = 0). Steps 1..3: + h@WhhL^T + whhr.
    lstm_elem_kernel<<<B, 256>>>(pGq, 1);
    for (int s = 1; s < 4; s++) {
        sgemm_kernel<<<dim3(8, 32), 256>>>(pH, 256, pWhhLp, 256, pGates, 1024,
                                           B, 1024, 256, pWhhr, pGq, 1024, 0);
        lstm_elem_kernel<<<B, 256>>>(pGates, 0);
    }

    // 8) final cosine similarity -> out (4096)
    final_kernel<<<B / 8, 256>>>(out);
}

// round 2
// speedup vs baseline: 1.7528x; 1.7528x over previous
#include <cuda_runtime.h>
#include <cuda_bf16.h>
#include <math.h>

// ---------------------------------------------------------------------------
// Problem constants
// ---------------------------------------------------------------------------
#define NSYM   100000
#define PADID  100000
#define DM     256
#define B      4096
#define FEW    5
#define MAXK   50
#define KNEI   10
#define EPS    1e-8f
#define LNEPS  1e-5f

// ---------------------------------------------------------------------------
// Scratch (device globals -- no allocations allowed)
// ---------------------------------------------------------------------------
__device__ __align__(128) float g_P[(NSYM + 1) * 256];     // [PR | PE] per symbol
__device__ __align__(128) float g_Wt[256 * 128];           // rearranged gcn W
__device__ __align__(128) float g_qvec[B * 256];
__device__ __align__(128) float g_svec[FEW * 256];
__device__ __align__(128) float g_sh1[FEW * 512];          // support MLP hidden
__device__ __align__(128) float g_sh[FEW * 256];           // support MLP out (pre-LN)
__device__ __align__(128) float g_sg[256];                 // support_g
__device__ __align__(128) float g_sgn[1];                  // sqrt(|sg|^2+eps)
__device__ __align__(128) float g_H1[B * 512];
__device__ __align__(128) float g_tmp[B * 256];
__device__ __align__(128) float g_X[B * 256];              // query_enc
__device__ __align__(128) float g_Wihp[1024 * 256];
__device__ __align__(128) float g_WhhLp[1024 * 256];
__device__ __align__(128) float g_bsum[1024];
__device__ __align__(128) float g_whhr[1024];
__device__ __align__(128) float g_Gq[B * 1024];
__device__ __align__(128) float g_gates[B * 1024];
__device__ __align__(128) float g_c[B * 256];
__device__ __align__(128) float g_h[B * 256];

__device__ __forceinline__ float sigf(float x) { return 1.f / (1.f + expf(-x)); }

// ---------------------------------------------------------------------------
// Generic SGEMM: C[M,N] = A[M,K] @ B[N,K]^T (+bias[n]) (+res[m,n]) (relu?)
// BM=BN=128, BK=8, 256 threads, 8x8 per thread.
// ---------------------------------------------------------------------------
__global__ void sgemm_kernel(const float* __restrict__ A, int lda,
                             const float* __restrict__ Bm, int ldb,
                             float* __restrict__ C, int ldc,
                             int M, int N, int K,
                             const float* __restrict__ bias,
                             const float* __restrict__ res, int ldres,
                             int relu)
{
    __shared__ __align__(16) float As[8][132];
    __shared__ __align__(16) float Bs[8][132];
    const int tid = threadIdx.x;
    const int bm = blockIdx.y * 128;
    const int bn = blockIdx.x * 128;
    const int ldr = tid >> 1;
    const int ldk = (tid & 1) * 4;
    const int ty  = tid >> 4;
    const int tx  = tid & 15;

    float acc[8][8];
#pragma unroll
    for (int i = 0; i < 8; i++)
#pragma unroll
        for (int j = 0; j < 8; j++) acc[i][j] = 0.f;

    const int grA = bm + ldr;
    const bool avalid = (grA < M);
    const float* Aptr = A + (size_t)grA * lda + ldk;
    const float* Bptr = Bm + (size_t)(bn + ldr) * ldb + ldk;

    for (int k0 = 0; k0 < K; k0 += 8) {
        float4 av = avalid ? *(const float4*)(Aptr + k0) : make_float4(0.f, 0.f, 0.f, 0.f);
        float4 bv = *(const float4*)(Bptr + k0);
        As[ldk + 0][ldr] = av.x; As[ldk + 1][ldr] = av.y;
        As[ldk + 2][ldr] = av.z; As[ldk + 3][ldr] = av.w;
        Bs[ldk + 0][ldr] = bv.x; Bs[ldk + 1][ldr] = bv.y;
        Bs[ldk + 2][ldr] = bv.z; Bs[ldk + 3][ldr] = bv.w;
        __syncthreads();
#pragma unroll
        for (int k = 0; k < 8; k++) {
            float a[8], b[8];
            *(float4*)&a[0] = *(const float4*)&As[k][ty * 8];
            *(float4*)&a[4] = *(const float4*)&As[k][ty * 8 + 4];
            *(float4*)&b[0] = *(const float4*)&Bs[k][tx * 8];
            *(float4*)&b[4] = *(const float4*)&Bs[k][tx * 8 + 4];
#pragma unroll
            for (int i = 0; i < 8; i++)
#pragma unroll
                for (int j = 0; j < 8; j++)
                    acc[i][j] = fmaf(a[i], b[j], acc[i][j]);
        }
        __syncthreads();
    }

#pragma unroll
    for (int i = 0; i < 8; i++) {
        int r = bm + ty * 8 + i;
        if (r < M) {
            float* crow = C + (size_t)r * ldc + bn + tx * 8;
            const float* rrow = res ? (res + (size_t)r * ldres + bn + tx * 8) : nullptr;
#pragma unroll
            for (int j = 0; j < 8; j++) {
                float v = acc[i][j];
                if (bias) v += bias[bn + tx * 8 + j];
                if (rrow) v += rrow[j];
                if (relu) v = fmaxf(v, 0.f);
                crow[j] = v;
            }
        }
    }
}

// ---------------------------------------------------------------------------
// Rearrange gcn_w_W (128 x 256) into Wt (256 x 128)
// ---------------------------------------------------------------------------
__global__ void pack_wt_kernel(const float* __restrict__ W)
{
    int n = blockIdx.x, k = threadIdx.x;
    g_Wt[n * 128 + k] = W[(n & 127) * 256 + ((n >> 7) << 7) + k];
}

// ---------------------------------------------------------------------------
// Neighbor encoder: one block (128 thr) per entity. 8202 entities.
// ---------------------------------------------------------------------------
__global__ void neighbor_kernel(const int* __restrict__ query,
                                const int* __restrict__ support,
                                const int* __restrict__ q_l1, const int* __restrict__ q_deg_l,
                                const int* __restrict__ q_r1, const int* __restrict__ q_deg_r,
                                const int* __restrict__ s_l1, const int* __restrict__ s_deg_l,
                                const int* __restrict__ s_r1, const int* __restrict__ s_deg_r,
                                const float* __restrict__ sym,
                                const float* __restrict__ gwb, const float* __restrict__ gb,
                                const float* __restrict__ gate_w,
                                const float* __restrict__ gate_temp)
{
    __shared__ float s_self[128], s_bias[128];
    __shared__ float s_proj[MAXK][128];
    __shared__ float s_cos[MAXK];
    __shared__ float s_gw[MAXK];
    __shared__ int   s_sel[KNEI];
    __shared__ float s_scal[2];

    int e = blockIdx.x;
    const int* conn; int sid, deg; float* outp;
    if (e < 4096)      { conn = q_l1 + e * 100;                sid = query[e * 2];           deg = q_deg_l[e];      outp = g_qvec + e * 256; }
    else if (e < 8192) { int i = e - 4096; conn = q_r1 + i * 100; sid = query[i * 2 + 1];   deg = q_deg_r[i];      outp = g_qvec + i * 256 + 128; }
    else if (e < 8197) { int i = e - 8192; conn = s_l1 + i * 100; sid = support[i * 2];     deg = s_deg_l[i];      outp = g_svec + i * 256; }
    else               { int i = e - 8197; conn = s_r1 + i * 100; sid = support[i * 2 + 1]; deg = s_deg_r[i];      outp = g_svec + i * 256 + 128; }

    int t = threadIdx.x, lane = t & 31, w = t >> 5;
    s_self[t] = sym[(size_t)sid * 128 + t];
    s_bias[t] = gwb[t] + gb[t];
    if (t < MAXK) { int r = conn[2 * t]; s_gw[t] = gate_w[(r == PADID) ? 0 : r]; }
    __syncthreads();

    if (w == 0) {
        float ss = 0.f;
#pragma unroll
        for (int i = 0; i < 4; i++) { float v = s_self[lane + 32 * i]; ss += v * v; }
        for (int o = 16; o > 0; o >>= 1) ss += __shfl_xor_sync(~0u, ss, o);
        if (lane == 0) s_scal[0] = sqrtf(ss + EPS);
    }
    __syncthreads();
    float nself = s_scal[0];

    for (int base = 0; base < 52; base += 4) {
        int n = base + w;
        if (n < MAXK) {
            int rel = conn[2 * n], ent = conn[2 * n + 1];
            const float* pr = g_P + (size_t)rel * 256;
            const float* pe = g_P + (size_t)ent * 256 + 128;
            float dp = 0.f, nn = 0.f;
#pragma unroll
            for (int i = 0; i < 4; i++) {
                int d = lane + 32 * i;
                float v = pr[d] + pe[d] + s_bias[d];
                v = (v > 0.f) ? v : 0.01f * v;
                if (rel == PADID) v = 0.f;
                s_proj[n][d] = v;
                dp += s_self[d] * v;
                nn += v * v;
            }
            for (int o = 16; o > 0; o >>= 1) {
                dp += __shfl_xor_sync(~0u, dp, o);
                nn += __shfl_xor_sync(~0u, nn, o);
            }
            if (lane == 0) {
                float nnei = sqrtf(nn + EPS);
                s_cos[n] = dp / (nself * nnei + EPS);
            }
        }
    }
    __syncthreads();

    if (t == 0) {
        unsigned long long used = 0ULL;
        for (int k = 0; k < KNEI; k++) {
            float best = -3.0e38f; int bi = 0;
            for (int i = 0; i < MAXK; i++) {
                if (!((used >> i) & 1ULL) && s_cos[i] > best) { best = s_cos[i]; bi = i; }
            }
            used |= 1ULL << bi;
            s_sel[k] = bi;
        }
        float gs = 0.f;
        for (int i = 0; i < MAXK; i++) gs += s_gw[i];
        gs = (gs / 50.f) / gate_temp[0];
        float gate = sigf(gs);
        if (deg <= 0) gate = 1.f;
        s_scal[1] = gate;
    }
    __syncthreads();

    float agg = 0.f;
#pragma unroll
    for (int k = 0; k < KNEI; k++) agg += s_proj[s_sel[k]][t];
    agg /= 10.f;
    outp[t] = tanhf(s_self[t] + s_scal[1] * agg);
}

// ---------------------------------------------------------------------------
// Support encoder, stage 1: sh1[r][j] = relu(svec[r] . W1[j] + b1[j])
// warp per output; FEW*512 = 2560 warps, 8 warps/block -> 320 blocks.
// ---------------------------------------------------------------------------
__global__ void se1_kernel(const float* __restrict__ W1, const float* __restrict__ b1)
{
    int gw = (blockIdx.x * blockDim.x + threadIdx.x) >> 5;
    int lane = threadIdx.x & 31;
    if (gw >= FEW * 512) return;
    int r = gw >> 9, j = gw & 511;
    const float4* x = (const float4*)(g_svec + r * 256);
    const float4* w = (const float4*)(W1 + (size_t)j * 256);
    float acc = 0.f;
#pragma unroll
    for (int k = lane; k < 64; k += 32) {
        float4 xv = x[k], wv = w[k];
        acc = fmaf(xv.x, wv.x, acc); acc = fmaf(xv.y, wv.y, acc);
        acc = fmaf(xv.z, wv.z, acc); acc = fmaf(xv.w, wv.w, acc);
    }
    for (int o = 16; o > 0; o >>= 1) acc += __shfl_xor_sync(~0u, acc, o);
    if (lane == 0) g_sh1[r * 512 + j] = fmaxf(acc + b1[j], 0.f);
}

// ---------------------------------------------------------------------------
// Support encoder, stage 2: sh[r][c] = sh1[r] . W2[c] + b2[c] + svec[r][c]
// warp per output; FEW*256 = 1280 warps -> 160 blocks.
// ---------------------------------------------------------------------------
__global__ void se2_kernel(const float* __restrict__ W2, const float* __restrict__ b2)
{
    int gw = (blockIdx.x * blockDim.x + threadIdx.x) >> 5;
    int lane = threadIdx.x & 31;
    if (gw >= FEW * 256) return;
    int r = gw >> 8, c = gw & 255;
    const float4* x = (const float4*)(g_sh1 + r * 512);
    const float4* w = (const float4*)(W2 + (size_t)c * 512);
    float acc = 0.f;
#pragma unroll
    for (int k = lane; k < 128; k += 32) {
        float4 xv = x[k], wv = w[k];
        acc = fmaf(xv.x, wv.x, acc); acc = fmaf(xv.y, wv.y, acc);
        acc = fmaf(xv.z, wv.z, acc); acc = fmaf(xv.w, wv.w, acc);
    }
    for (int o = 16; o > 0; o >>= 1) acc += __shfl_xor_sync(~0u, acc, o);
    if (lane == 0) g_sh[r * 256 + c] = acc + b2[c] + g_svec[r * 256 + c];
}

// ---------------------------------------------------------------------------
// Support encoder, stage 3: per-row LN over g_sh (5 x 256), mean over rows
// -> g_sg; then ||sg||. One block, 256 threads.
// ---------------------------------------------------------------------------
__global__ void se3_kernel(const float* __restrict__ g, const float* __restrict__ b)
{
    __shared__ float smu[FEW], srs[FEW];
    __shared__ float red[8];
    int t = threadIdx.x, lane = t & 31, w = t >> 5;

    if (w < FEW) {   // warp w handles row w: mean + var over 256 elems (8/lane)
        const float* row = g_sh + w * 256;
        float s = 0.f;
#pragma unroll
        for (int i = 0; i < 8; i++) s += row[lane + 32 * i];
        for (int o = 16; o > 0; o >>= 1) s += __shfl_xor_sync(~0u, s, o);
        float mu = s / 256.f;
        float q = 0.f;
#pragma unroll
        for (int i = 0; i < 8; i++) { float d = row[lane + 32 * i] - mu; q += d * d; }
        for (int o = 16; o > 0; o >>= 1) q += __shfl_xor_sync(~0u, q, o);
        if (lane == 0) { smu[w] = mu; srs[w] = 1.f / sqrtf(q / 256.f + LNEPS); }
    }
    __syncthreads();

    float acc = 0.f;
#pragma unroll
    for (int r = 0; r < FEW; r++)
        acc += g[t] * (g_sh[r * 256 + t] - smu[r]) * srs[r] + b[t];
    acc *= 0.2f;
    g_sg[t] = acc;

    float nq = acc * acc;
    for (int o = 16; o > 0; o >>= 1) nq += __shfl_xor_sync(~0u, nq, o);
    if (lane == 0) red[w] = nq;
    __syncthreads();
    if (t == 0) {
        float s = 0.f;
        for (int i = 0; i < 8; i++) s += red[i];
        g_sgn[0] = sqrtf(s + EPS);
    }
}

// ---------------------------------------------------------------------------
// LSTM prep: pack live gate rows + bias sum + constant r contribution.
// ---------------------------------------------------------------------------
__global__ void prep_lstm_kernel(const float* __restrict__ Wih, const float* __restrict__ Whh,
                                 const float* __restrict__ bih, const float* __restrict__ bhh)
{
    int j = blockIdx.x;                 // 0..1023
    int grp = j >> 8, within = j & 255;
    int jm = grp * 512 + within;
    int t = threadIdx.x;                // 256
    g_Wihp[j * 256 + t]  = Wih[jm * 256 + t];
    g_WhhLp[j * 256 + t] = Whh[jm * 512 + t];
    float p = g_sg[t] * Whh[jm * 512 + 256 + t];
    __shared__ float red[8];
    for (int o = 16; o > 0; o >>= 1) p += __shfl_xor_sync(~0u, p, o);
    if ((t & 31) == 0) red[t >> 5] = p;
    __syncthreads();
    if (t == 0) {
        float s = 0.f;
        for (int i = 0; i < 8; i++) s += red[i];
        g_whhr[j] = s;
        g_bsum[j] = bih[jm] + bhh[jm];
    }
}

// ---------------------------------------------------------------------------
// LayerNorm rows of g_tmp -> g_X (4096 rows x 256)
// ---------------------------------------------------------------------------
__global__ void ln_kernel(const float* __restrict__ g, const float* __restrict__ b)
{
    int row = blockIdx.x, t = threadIdx.x;
    float v = g_tmp[(size_t)row * 256 + t];
    __shared__ float red[8];
    __shared__ float s_mu, s_rs;
    float s = v;
    for (int o = 16; o > 0; o >>= 1) s += __shfl_xor_sync(~0u, s, o);
    if ((t & 31) == 0) red[t >> 5] = s;
    __syncthreads();
    if (t == 0) { float m = 0.f; for (int i = 0; i < 8; i++) m += red[i]; s_mu = m / 256.f; }
    __syncthreads();
    float d = v - s_mu;
    float q = d * d;
    for (int o = 16; o > 0; o >>= 1) q += __shfl_xor_sync(~0u, q, o);
    if ((t & 31) == 0) red[t >> 5] = q;
    __syncthreads();
    if (t == 0) { float m = 0.f; for (int i = 0; i < 8; i++) m += red[i]; s_rs = 1.f / sqrtf(m / 256.f + LNEPS); }
    __syncthreads();
    g_X[(size_t)row * 256 + t] = g[t] * d * s_rs + b[t];
}

// ---------------------------------------------------------------------------
// LSTM elementwise step.
// ---------------------------------------------------------------------------
__global__ void lstm_elem_kernel(const float* __restrict__ gates, int first)
{
    int row = blockIdx.x, t = threadIdx.x;
    const float* gr = gates + (size_t)row * 1024;
    float gi = gr[t], gf = gr[256 + t], gg = gr[512 + t], go = gr[768 + t];
    float c = first ? 0.f : g_c[(size_t)row * 256 + t];
    c = sigf(gf) * c + sigf(gi) * tanhf(gg);
    g_c[(size_t)row * 256 + t] = c;
    g_h[(size_t)row * 256 + t] = g_X[(size_t)row * 256 + t] + sigf(go) * tanhf(c);
}

// ---------------------------------------------------------------------------
// Final cosine vs support_g.
// ---------------------------------------------------------------------------
__global__ void final_kernel(float* __restrict__ out)
{
    __shared__ float ssg[256];
    int t = threadIdx.x, lane = t & 31, w = t >> 5;
    ssg[t] = g_sg[t];
    __syncthreads();
    int row = blockIdx.x * 8 + w;
    const float* h = g_h + (size_t)row * 256;
    float dp = 0.f, nq = 0.f;
#pragma unroll
    for (int i = 0; i < 8; i++) {
        int d = lane + 32 * i;
        float v = h[d];
        dp += v * ssg[d];
        nq += v * v;
    }
    for (int o = 16; o > 0; o >>= 1) {
        dp += __shfl_xor_sync(~0u, dp, o);
        nq += __shfl_xor_sync(~0u, nq, o);
    }
    if (lane == 0) out[row] = dp / (sqrtf(nq + EPS) * g_sgn[0]);
}

// ---------------------------------------------------------------------------
// kernel_launch
// ---------------------------------------------------------------------------
extern "C" void kernel_launch(void* const* d_in, const int* in_sizes, int n_in,
                              void* d_out, int out_size)
{
    const int*   query     = (const int*)d_in[0];
    const int*   support   = (const int*)d_in[1];
    const int*   q_l1      = (const int*)d_in[2];
    const int*   q_deg_l   = (const int*)d_in[3];
    const int*   q_r1      = (const int*)d_in[4];
    const int*   q_deg_r   = (const int*)d_in[5];
    const int*   s_l1      = (const int*)d_in[6];
    const int*   s_deg_l   = (const int*)d_in[7];
    const int*   s_r1      = (const int*)d_in[8];
    const int*   s_deg_r   = (const int*)d_in[9];
    const float* sym       = (const float*)d_in[10];
    const float* gcn_w_W   = (const float*)d_in[11];
    const float* gcn_w_b   = (const float*)d_in[12];
    const float* gcn_b     = (const float*)d_in[13];
    const float* gate_w    = (const float*)d_in[14];
    const float* gate_temp = (const float*)d_in[15];
    const float* se_W1     = (const float*)d_in[16];
    const float* se_b1     = (const float*)d_in[17];
    const float* se_W2     = (const float*)d_in[18];
    const float* se_b2     = (const float*)d_in[19];
    const float* ln_g      = (const float*)d_in[20];
    const float* ln_b      = (const float*)d_in[21];
    const float* lstm_Wih  = (const float*)d_in[22];
    const float* lstm_Whh  = (const float*)d_in[23];
    const float* lstm_bih  = (const float*)d_in[24];
    const float* lstm_bhh  = (const float*)d_in[25];
    float* out = (float*)d_out;

    float *pP, *pWt, *pQv, *pH1, *pTmp, *pX, *pWihp, *pWhhLp, *pBsum, *pWhhr, *pGq, *pGates, *pH;
    cudaGetSymbolAddress((void**)&pP,     g_P);
    cudaGetSymbolAddress((void**)&pWt,    g_Wt);
    cudaGetSymbolAddress((void**)&pQv,    g_qvec);
    cudaGetSymbolAddress((void**)&pH1,    g_H1);
    cudaGetSymbolAddress((void**)&pTmp,   g_tmp);
    cudaGetSymbolAddress((void**)&pX,     g_X);
    cudaGetSymbolAddress((void**)&pWihp,  g_Wihp);
    cudaGetSymbolAddress((void**)&pWhhLp, g_WhhLp);
    cudaGetSymbolAddress((void**)&pBsum,  g_bsum);
    cudaGetSymbolAddress((void**)&pWhhr,  g_whhr);
    cudaGetSymbolAddress((void**)&pGq,    g_Gq);
    cudaGetSymbolAddress((void**)&pGates, g_gates);
    cudaGetSymbolAddress((void**)&pH,     g_h);

    // 1) P = sym_emb @ Wt^T  (100001 x 256, K=128)
    pack_wt_kernel<<<256, 128>>>(gcn_w_W);
    sgemm_kernel<<<dim3(2, (NSYM + 1 + 127) / 128), 256>>>(
        sym, 128, pWt, 128, pP, 256, NSYM + 1, 256, 128, nullptr, nullptr, 0, 0);

    // 2) neighbor encoder -> g_qvec, g_svec
    neighbor_kernel<<<8202, 128>>>(query, support, q_l1, q_deg_l, q_r1, q_deg_r,
                                   s_l1, s_deg_l, s_r1, s_deg_r,
                                   sym, gcn_w_b, gcn_b, gate_w, gate_temp);

    // 3) support encoder (grid-parallel) -> g_sg, g_sgn
    se1_kernel<<<(FEW * 512 + 7) / 8, 256>>>(se_W1, se_b1);
    se2_kernel<<<(FEW * 256 + 7) / 8, 256>>>(se_W2, se_b2);
    se3_kernel<<<1, 256>>>(ln_g, ln_b);

    // 4) LSTM weight packing + constants (needs g_sg)
    prep_lstm_kernel<<<1024, 256>>>(lstm_Wih, lstm_Whh, lstm_bih, lstm_bhh);

    // 5) query support-encoder + LN
    sgemm_kernel<<<dim3(4, 32), 256>>>(pQv, 256, se_W1, 256, pH1, 512,
                                       B, 512, 256, se_b1, nullptr, 0, 1);
    sgemm_kernel<<<dim3(2, 32), 256>>>(pH1, 512, se_W2, 512, pTmp, 256,
                                       B, 256, 512, se_b2, pQv, 256, 0);
    ln_kernel<<<B, 256>>>(ln_g, ln_b);

    // 6) Gq = X @ Wihp^T + (bih+bhh)
    sgemm_kernel<<<dim3(8, 32), 256>>>(pX, 256, pWihp, 256, pGq, 1024,
                                       B, 1024, 256, pBsum, nullptr, 0, 0);

    // 7) LSTM steps
    lstm_elem_kernel<<<B, 256>>>(pGq, 1);
    for (int s = 1; s < 4; s++) {
        sgemm_kernel<<<dim3(8, 32), 256>>>(pH, 256, pWhhLp, 256, pGates, 1024,
                                           B, 1024, 256, pWhhr, pGq, 1024, 0);
        lstm_elem_kernel<<<B, 256>>>(pGates, 0);
    }

    // 8) final cosine
    final_kernel<<<B / 8, 256>>>(out);
}

// round 3
// speedup vs baseline: 2.8186x; 1.6081x over previous
#include <cuda_runtime.h>
#include <cuda_bf16.h>
#include <math.h>
#include <stdint.h>

// ---------------------------------------------------------------------------
// Problem constants
// ---------------------------------------------------------------------------
#define NSYM   100000
#define PADID  100000
#define B      4096
#define FEW    5
#define MAXK   50
#define KNEI   10
#define EPS    1e-8f
#define LNEPS  1e-5f

// ---------------------------------------------------------------------------
// Scratch (device globals -- no allocations allowed)
// ---------------------------------------------------------------------------
__device__ __align__(128) float g_P[(NSYM + 1) * 256];
__device__ __align__(128) float g_Wt[256 * 128];
__device__ __align__(128) float g_qvec[B * 256];
__device__ __align__(128) float g_svec[FEW * 256];
__device__ __align__(128) float g_sh1[FEW * 512];
__device__ __align__(128) float g_sh[FEW * 256];
__device__ __align__(128) float g_sg[256];
__device__ __align__(128) float g_sgn[1];
__device__ __align__(128) float g_H1[B * 512];
__device__ __align__(128) float g_tmp[B * 256];
__device__ __align__(128) float g_X[B * 256];
__device__ __align__(128) float g_Wihp[1024 * 256];
__device__ __align__(128) float g_WhhLp[1024 * 256];
__device__ __align__(128) float g_bsum[1024];
__device__ __align__(128) float g_whhr[1024];
__device__ __align__(128) float g_Gq[B * 1024];
__device__ __align__(128) float g_gates[B * 1024];
__device__ __align__(128) float g_c[B * 256];
__device__ __align__(128) float g_h[B * 256];

__device__ __forceinline__ float sigf(float x) { return 1.f / (1.f + expf(-x)); }

__device__ __forceinline__ uint32_t f2tf32(float x) {
    uint32_t r;
    asm("cvt.rna.tf32.f32 %0, %1;" : "=r"(r) : "f"(x));
    return r;
}

#define MMA_TF32(d, a, b)                                                     \
    asm volatile("mma.sync.aligned.m16n8k8.row.col.f32.tf32.tf32.f32 "        \
                 "{%0,%1,%2,%3}, {%4,%5,%6,%7}, {%8,%9}, {%0,%1,%2,%3};"      \
                 : "+f"(d[0]), "+f"(d[1]), "+f"(d[2]), "+f"(d[3])             \
                 : "r"(a[0]), "r"(a[1]), "r"(a[2]), "r"(a[3]),                \
                   "r"(b[0]), "r"(b[1]))

// ---------------------------------------------------------------------------
// TF32 tensor-core GEMM: C[M,N] = A[M,K] @ B[N,K]^T (+bias[n]) (+res) (relu?)
// BM=BN=128, BK=32, 256 threads (8 warps, 2x4), warp tile 64x32.
// SPLIT=1: split-tf32 (hi/lo) for near-fp32 accuracy (3 MMAs per step).
// Requires: N % 128 == 0, K % 32 == 0. M guarded.
// smem stride = 36 floats (pad 4) -> conflict-free fragment loads.
// ---------------------------------------------------------------------------
#define SMS 36
template <int SPLIT>
__global__ __launch_bounds__(256) void tgemm_kernel(
    const float* __restrict__ A, int lda,
    const float* __restrict__ Bm, int ldb,
    float* __restrict__ C, int ldc,
    int M, int N, int K,
    const float* __restrict__ bias,
    const float* __restrict__ res, int ldres,
    int relu)
{
    extern __shared__ float sm[];
    float* sAh = sm;
    float* sBh = sm + 128 * SMS;
    float* sAl = SPLIT ? sm + 2 * 128 * SMS : sm;
    float* sBl = SPLIT ? sm + 3 * 128 * SMS : sm;

    const int tid = threadIdx.x;
    const int bm = blockIdx.y * 128;
    const int bn = blockIdx.x * 128;
    const int wid = tid >> 5, lane = tid & 31;
    const int wm = (wid >> 2) * 64, wn = (wid & 3) * 32;
    const int gr = lane >> 2, gc = lane & 3;
    const int lrow = tid >> 3;          // 0..31
    const int lcol = (tid & 7) * 4;     // 0,4,..28

    float acc[4][4][4];
#pragma unroll
    for (int i = 0; i < 4; i++)
#pragma unroll
        for (int j = 0; j < 4; j++)
#pragma unroll
            for (int k = 0; k < 4; k++) acc[i][j][k] = 0.f;

    for (int k0 = 0; k0 < K; k0 += 32) {
#pragma unroll
        for (int p = 0; p < 4; p++) {
            int row = p * 32 + lrow;
            int ga = bm + row;
            float4 va = (ga < M) ? *(const float4*)(A + (size_t)ga * lda + k0 + lcol)
                                 : make_float4(0.f, 0.f, 0.f, 0.f);
            float4 vb = *(const float4*)(Bm + (size_t)(bn + row) * ldb + k0 + lcol);
            float av[4] = {va.x, va.y, va.z, va.w};
            float bv[4] = {vb.x, vb.y, vb.z, vb.w};
#pragma unroll
            for (int i = 0; i < 4; i++) {
                uint32_t ah = f2tf32(av[i]);
                uint32_t bh = f2tf32(bv[i]);
                sAh[row * SMS + lcol + i] = __uint_as_float(ah);
                sBh[row * SMS + lcol + i] = __uint_as_float(bh);
                if (SPLIT) {
                    sAl[row * SMS + lcol + i] = __uint_as_float(f2tf32(av[i] - __uint_as_float(ah)));
                    sBl[row * SMS + lcol + i] = __uint_as_float(f2tf32(bv[i] - __uint_as_float(bh)));
                }
            }
        }
        __syncthreads();

#pragma unroll
        for (int ks = 0; ks < 4; ks++) {
            int kb = ks * 8;
            uint32_t ah[4][4], al[4][4], bh[4][2], bl[4][2];
#pragma unroll
            for (int mi = 0; mi < 4; mi++) {
                int base = (wm + mi * 16 + gr) * SMS + kb + gc;
                ah[mi][0] = __float_as_uint(sAh[base]);
                ah[mi][1] = __float_as_uint(sAh[base + 8 * SMS]);
                ah[mi][2] = __float_as_uint(sAh[base + 4]);
                ah[mi][3] = __float_as_uint(sAh[base + 8 * SMS + 4]);
                if (SPLIT) {
                    al[mi][0] = __float_as_uint(sAl[base]);
                    al[mi][1] = __float_as_uint(sAl[base + 8 * SMS]);
                    al[mi][2] = __float_as_uint(sAl[base + 4]);
                    al[mi][3] = __float_as_uint(sAl[base + 8 * SMS + 4]);
                }
            }
#pragma unroll
            for (int ni = 0; ni < 4; ni++) {
                int base = (wn + ni * 8 + gr) * SMS + kb + gc;
                bh[ni][0] = __float_as_uint(sBh[base]);
                bh[ni][1] = __float_as_uint(sBh[base + 4]);
                if (SPLIT) {
                    bl[ni][0] = __float_as_uint(sBl[base]);
                    bl[ni][1] = __float_as_uint(sBl[base + 4]);
                }
            }
#pragma unroll
            for (int mi = 0; mi < 4; mi++)
#pragma unroll
                for (int ni = 0; ni < 4; ni++) {
                    MMA_TF32(acc[mi][ni], ah[mi], bh[ni]);
                    if (SPLIT) {
                        MMA_TF32(acc[mi][ni], ah[mi], bl[ni]);
                        MMA_TF32(acc[mi][ni], al[mi], bh[ni]);
                    }
                }
        }
        __syncthreads();
    }

    // Epilogue
#pragma unroll
    for (int mi = 0; mi < 4; mi++) {
#pragma unroll
        for (int ni = 0; ni < 4; ni++) {
            int col = bn + wn + ni * 8 + gc * 2;
            float b0 = bias ? bias[col] : 0.f;
            float b1 = bias ? bias[col + 1] : 0.f;
#pragma unroll
            for (int half = 0; half < 2; half++) {
                int r = bm + wm + mi * 16 + gr + half * 8;
                if (r < M) {
                    float v0 = acc[mi][ni][half * 2 + 0] + b0;
                    float v1 = acc[mi][ni][half * 2 + 1] + b1;
                    if (res) {
                        v0 += res[(size_t)r * ldres + col];
                        v1 += res[(size_t)r * ldres + col + 1];
                    }
                    if (relu) { v0 = fmaxf(v0, 0.f); v1 = fmaxf(v1, 0.f); }
                    C[(size_t)r * ldc + col]     = v0;
                    C[(size_t)r * ldc + col + 1] = v1;
                }
            }
        }
    }
}

// ---------------------------------------------------------------------------
// Rearrange gcn_w_W (128 x 256) into Wt (256 x 128)
// ---------------------------------------------------------------------------
__global__ void pack_wt_kernel(const float* __restrict__ W)
{
    int n = blockIdx.x, k = threadIdx.x;
    g_Wt[n * 128 + k] = W[(n & 127) * 256 + ((n >> 7) << 7) + k];
}

// ---------------------------------------------------------------------------
// Neighbor encoder: one block (128 thr) per entity. 8202 entities.
// ---------------------------------------------------------------------------
__global__ void neighbor_kernel(const int* __restrict__ query,
                                const int* __restrict__ support,
                                const int* __restrict__ q_l1, const int* __restrict__ q_deg_l,
                                const int* __restrict__ q_r1, const int* __restrict__ q_deg_r,
                                const int* __restrict__ s_l1, const int* __restrict__ s_deg_l,
                                const int* __restrict__ s_r1, const int* __restrict__ s_deg_r,
                                const float* __restrict__ sym,
                                const float* __restrict__ gwb, const float* __restrict__ gb,
                                const float* __restrict__ gate_w,
                                const float* __restrict__ gate_temp)
{
    __shared__ float s_self[128], s_bias[128];
    __shared__ float s_proj[MAXK][128];
    __shared__ float s_cos[MAXK];
    __shared__ float s_gw[MAXK];
    __shared__ int   s_sel[KNEI];
    __shared__ float s_scal[2];

    int e = blockIdx.x;
    const int* conn; int sid, deg; float* outp;
    if (e < 4096)      { conn = q_l1 + e * 100;                sid = query[e * 2];           deg = q_deg_l[e];      outp = g_qvec + e * 256; }
    else if (e < 8192) { int i = e - 4096; conn = q_r1 + i * 100; sid = query[i * 2 + 1];   deg = q_deg_r[i];      outp = g_qvec + i * 256 + 128; }
    else if (e < 8197) { int i = e - 8192; conn = s_l1 + i * 100; sid = support[i * 2];     deg = s_deg_l[i];      outp = g_svec + i * 256; }
    else               { int i = e - 8197; conn = s_r1 + i * 100; sid = support[i * 2 + 1]; deg = s_deg_r[i];      outp = g_svec + i * 256 + 128; }

    int t = threadIdx.x, lane = t & 31, w = t >> 5;
    s_self[t] = sym[(size_t)sid * 128 + t];
    s_bias[t] = gwb[t] + gb[t];
    if (t < MAXK) { int r = conn[2 * t]; s_gw[t] = gate_w[(r == PADID) ? 0 : r]; }
    __syncthreads();

    if (w == 0) {
        float ss = 0.f;
#pragma unroll
        for (int i = 0; i < 4; i++) { float v = s_self[lane + 32 * i]; ss += v * v; }
        for (int o = 16; o > 0; o >>= 1) ss += __shfl_xor_sync(~0u, ss, o);
        if (lane == 0) s_scal[0] = sqrtf(ss + EPS);
    }
    __syncthreads();
    float nself = s_scal[0];

    for (int base = 0; base < 52; base += 4) {
        int n = base + w;
        if (n < MAXK) {
            int rel = conn[2 * n], ent = conn[2 * n + 1];
            const float* pr = g_P + (size_t)rel * 256;
            const float* pe = g_P + (size_t)ent * 256 + 128;
            float dp = 0.f, nn = 0.f;
#pragma unroll
            for (int i = 0; i < 4; i++) {
                int d = lane + 32 * i;
                float v = pr[d] + pe[d] + s_bias[d];
                v = (v > 0.f) ? v : 0.01f * v;
                if (rel == PADID) v = 0.f;
                s_proj[n][d] = v;
                dp += s_self[d] * v;
                nn += v * v;
            }
            for (int o = 16; o > 0; o >>= 1) {
                dp += __shfl_xor_sync(~0u, dp, o);
                nn += __shfl_xor_sync(~0u, nn, o);
            }
            if (lane == 0) {
                float nnei = sqrtf(nn + EPS);
                s_cos[n] = dp / (nself * nnei + EPS);
            }
        }
    }
    __syncthreads();

    if (t == 0) {
        unsigned long long used = 0ULL;
        for (int k = 0; k < KNEI; k++) {
            float best = -3.0e38f; int bi = 0;
            for (int i = 0; i < MAXK; i++) {
                if (!((used >> i) & 1ULL) && s_cos[i] > best) { best = s_cos[i]; bi = i; }
            }
            used |= 1ULL << bi;
            s_sel[k] = bi;
        }
        float gs = 0.f;
        for (int i = 0; i < MAXK; i++) gs += s_gw[i];
        gs = (gs / 50.f) / gate_temp[0];
        float gate = sigf(gs);
        if (deg <= 0) gate = 1.f;
        s_scal[1] = gate;
    }
    __syncthreads();

    float agg = 0.f;
#pragma unroll
    for (int k = 0; k < KNEI; k++) agg += s_proj[s_sel[k]][t];
    agg /= 10.f;
    outp[t] = tanhf(s_self[t] + s_scal[1] * agg);
}

// ---------------------------------------------------------------------------
// Support encoder stages (small, grid-parallel warp-GEMV)
// ---------------------------------------------------------------------------
__global__ void se1_kernel(const float* __restrict__ W1, const float* __restrict__ b1)
{
    int gw = (blockIdx.x * blockDim.x + threadIdx.x) >> 5;
    int lane = threadIdx.x & 31;
    if (gw >= FEW * 512) return;
    int r = gw >> 9, j = gw & 511;
    const float4* x = (const float4*)(g_svec + r * 256);
    const float4* w = (const float4*)(W1 + (size_t)j * 256);
    float acc = 0.f;
#pragma unroll
    for (int k = lane; k < 64; k += 32) {
        float4 xv = x[k], wv = w[k];
        acc = fmaf(xv.x, wv.x, acc); acc = fmaf(xv.y, wv.y, acc);
        acc = fmaf(xv.z, wv.z, acc); acc = fmaf(xv.w, wv.w, acc);
    }
    for (int o = 16; o > 0; o >>= 1) acc += __shfl_xor_sync(~0u, acc, o);
    if (lane == 0) g_sh1[r * 512 + j] = fmaxf(acc + b1[j], 0.f);
}

__global__ void se2_kernel(const float* __restrict__ W2, const float* __restrict__ b2)
{
    int gw = (blockIdx.x * blockDim.x + threadIdx.x) >> 5;
    int lane = threadIdx.x & 31;
    if (gw >= FEW * 256) return;
    int r = gw >> 8, c = gw & 255;
    const float4* x = (const float4*)(g_sh1 + r * 512);
    const float4* w = (const float4*)(W2 + (size_t)c * 512);
    float acc = 0.f;
#pragma unroll
    for (int k = lane; k < 128; k += 32) {
        float4 xv = x[k], wv = w[k];
        acc = fmaf(xv.x, wv.x, acc); acc = fmaf(xv.y, wv.y, acc);
        acc = fmaf(xv.z, wv.z, acc); acc = fmaf(xv.w, wv.w, acc);
    }
    for (int o = 16; o > 0; o >>= 1) acc += __shfl_xor_sync(~0u, acc, o);
    if (lane == 0) g_sh[r * 256 + c] = acc + b2[c] + g_svec[r * 256 + c];
}

__global__ void se3_kernel(const float* __restrict__ g, const float* __restrict__ b)
{
    __shared__ float smu[FEW], srs[FEW];
    __shared__ float red[8];
    int t = threadIdx.x, lane = t & 31, w = t >> 5;

    if (w < FEW) {
        const float* row = g_sh + w * 256;
        float s = 0.f;
#pragma unroll
        for (int i = 0; i < 8; i++) s += row[lane + 32 * i];
        for (int o = 16; o > 0; o >>= 1) s += __shfl_xor_sync(~0u, s, o);
        float mu = s / 256.f;
        float q = 0.f;
#pragma unroll
        for (int i = 0; i < 8; i++) { float d = row[lane + 32 * i] - mu; q += d * d; }
        for (int o = 16; o > 0; o >>= 1) q += __shfl_xor_sync(~0u, q, o);
        if (lane == 0) { smu[w] = mu; srs[w] = 1.f / sqrtf(q / 256.f + LNEPS); }
    }
    __syncthreads();

    float acc = 0.f;
#pragma unroll
    for (int r = 0; r < FEW; r++)
        acc += g[t] * (g_sh[r * 256 + t] - smu[r]) * srs[r] + b[t];
    acc *= 0.2f;
    g_sg[t] = acc;

    float nq = acc * acc;
    for (int o = 16; o > 0; o >>= 1) nq += __shfl_xor_sync(~0u, nq, o);
    if (lane == 0) red[w] = nq;
    __syncthreads();
    if (t == 0) {
        float s = 0.f;
        for (int i = 0; i < 8; i++) s += red[i];
        g_sgn[0] = sqrtf(s + EPS);
    }
}

// ---------------------------------------------------------------------------
// LSTM prep
// ---------------------------------------------------------------------------
__global__ void prep_lstm_kernel(const float* __restrict__ Wih, const float* __restrict__ Whh,
                                 const float* __restrict__ bih, const float* __restrict__ bhh)
{
    int j = blockIdx.x;
    int grp = j >> 8, within = j & 255;
    int jm = grp * 512 + within;
    int t = threadIdx.x;
    g_Wihp[j * 256 + t]  = Wih[jm * 256 + t];
    g_WhhLp[j * 256 + t] = Whh[jm * 512 + t];
    float p = g_sg[t] * Whh[jm * 512 + 256 + t];
    __shared__ float red[8];
    for (int o = 16; o > 0; o >>= 1) p += __shfl_xor_sync(~0u, p, o);
    if ((t & 31) == 0) red[t >> 5] = p;
    __syncthreads();
    if (t == 0) {
        float s = 0.f;
        for (int i = 0; i < 8; i++) s += red[i];
        g_whhr[j] = s;
        g_bsum[j] = bih[jm] + bhh[jm];
    }
}

// ---------------------------------------------------------------------------
// LayerNorm rows of g_tmp -> g_X
// ---------------------------------------------------------------------------
__global__ void ln_kernel(const float* __restrict__ g, const float* __restrict__ b)
{
    int row = blockIdx.x, t = threadIdx.x;
    float v = g_tmp[(size_t)row * 256 + t];
    __shared__ float red[8];
    __shared__ float s_mu, s_rs;
    float s = v;
    for (int o = 16; o > 0; o >>= 1) s += __shfl_xor_sync(~0u, s, o);
    if ((t & 31) == 0) red[t >> 5] = s;
    __syncthreads();
    if (t == 0) { float m = 0.f; for (int i = 0; i < 8; i++) m += red[i]; s_mu = m / 256.f; }
    __syncthreads();
    float d = v - s_mu;
    float q = d * d;
    for (int o = 16; o > 0; o >>= 1) q += __shfl_xor_sync(~0u, q, o);
    if ((t & 31) == 0) red[t >> 5] = q;
    __syncthreads();
    if (t == 0) { float m = 0.f; for (int i = 0; i < 8; i++) m += red[i]; s_rs = 1.f / sqrtf(m / 256.f + LNEPS); }
    __syncthreads();
    g_X[(size_t)row * 256 + t] = g[t] * d * s_rs + b[t];
}

// ---------------------------------------------------------------------------
// LSTM elementwise step
// ---------------------------------------------------------------------------
__global__ void lstm_elem_kernel(const float* __restrict__ gates, int first)
{
    int row = blockIdx.x, t = threadIdx.x;
    const float* gr = gates + (size_t)row * 1024;
    float gi = gr[t], gf = gr[256 + t], gg = gr[512 + t], go = gr[768 + t];
    float c = first ? 0.f : g_c[(size_t)row * 256 + t];
    c = sigf(gf) * c + sigf(gi) * tanhf(gg);
    g_c[(size_t)row * 256 + t] = c;
    g_h[(size_t)row * 256 + t] = g_X[(size_t)row * 256 + t] + sigf(go) * tanhf(c);
}

// ---------------------------------------------------------------------------
// Final cosine vs support_g
// ---------------------------------------------------------------------------
__global__ void final_kernel(float* __restrict__ out)
{
    __shared__ float ssg[256];
    int t = threadIdx.x, lane = t & 31, w = t >> 5;
    ssg[t] = g_sg[t];
    __syncthreads();
    int row = blockIdx.x * 8 + w;
    const float* h = g_h + (size_t)row * 256;
    float dp = 0.f, nq = 0.f;
#pragma unroll
    for (int i = 0; i < 8; i++) {
        int d = lane + 32 * i;
        float v = h[d];
        dp += v * ssg[d];
        nq += v * v;
    }
    for (int o = 16; o > 0; o >>= 1) {
        dp += __shfl_xor_sync(~0u, dp, o);
        nq += __shfl_xor_sync(~0u, nq, o);
    }
    if (lane == 0) out[row] = dp / (sqrtf(nq + EPS) * g_sgn[0]);
}

// ---------------------------------------------------------------------------
// kernel_launch
// ---------------------------------------------------------------------------
extern "C" void kernel_launch(void* const* d_in, const int* in_sizes, int n_in,
                              void* d_out, int out_size)
{
    const int*   query     = (const int*)d_in[0];
    const int*   support   = (const int*)d_in[1];
    const int*   q_l1      = (const int*)d_in[2];
    const int*   q_deg_l   = (const int*)d_in[3];
    const int*   q_r1      = (const int*)d_in[4];
    const int*   q_deg_r   = (const int*)d_in[5];
    const int*   s_l1      = (const int*)d_in[6];
    const int*   s_deg_l   = (const int*)d_in[7];
    const int*   s_r1      = (const int*)d_in[8];
    const int*   s_deg_r   = (const int*)d_in[9];
    const float* sym       = (const float*)d_in[10];
    const float* gcn_w_W   = (const float*)d_in[11];
    const float* gcn_w_b   = (const float*)d_in[12];
    const float* gcn_b     = (const float*)d_in[13];
    const float* gate_w    = (const float*)d_in[14];
    const float* gate_temp = (const float*)d_in[15];
    const float* se_W1     = (const float*)d_in[16];
    const float* se_b1     = (const float*)d_in[17];
    const float* se_W2     = (const float*)d_in[18];
    const float* se_b2     = (const float*)d_in[19];
    const float* ln_g      = (const float*)d_in[20];
    const float* ln_b      = (const float*)d_in[21];
    const float* lstm_Wih  = (const float*)d_in[22];
    const float* lstm_Whh  = (const float*)d_in[23];
    const float* lstm_bih  = (const float*)d_in[24];
    const float* lstm_bhh  = (const float*)d_in[25];
    float* out = (float*)d_out;

    float *pP, *pWt, *pQv, *pH1, *pTmp, *pX, *pWihp, *pWhhLp, *pBsum, *pWhhr, *pGq, *pGates, *pH;
    cudaGetSymbolAddress((void**)&pP,     g_P);
    cudaGetSymbolAddress((void**)&pWt,    g_Wt);
    cudaGetSymbolAddress((void**)&pQv,    g_qvec);
    cudaGetSymbolAddress((void**)&pH1,    g_H1);
    cudaGetSymbolAddress((void**)&pTmp,   g_tmp);
    cudaGetSymbolAddress((void**)&pX,     g_X);
    cudaGetSymbolAddress((void**)&pWihp,  g_Wihp);
    cudaGetSymbolAddress((void**)&pWhhLp, g_WhhLp);
    cudaGetSymbolAddress((void**)&pBsum,  g_bsum);
    cudaGetSymbolAddress((void**)&pWhhr,  g_whhr);
    cudaGetSymbolAddress((void**)&pGq,    g_Gq);
    cudaGetSymbolAddress((void**)&pGates, g_gates);
    cudaGetSymbolAddress((void**)&pH,     g_h);

    const int SM1 = 2 * 128 * SMS * (int)sizeof(float);   // 36864
    const int SM2 = 4 * 128 * SMS * (int)sizeof(float);   // 73728
    static int attr_done = 0;
    if (!attr_done) {
        cudaFuncSetAttribute(tgemm_kernel<0>, cudaFuncAttributeMaxDynamicSharedMemorySize, SM1);
        cudaFuncSetAttribute(tgemm_kernel<1>, cudaFuncAttributeMaxDynamicSharedMemorySize, SM2);
        attr_done = 1;
    }

    // 1) P = sym_emb @ Wt^T  (100001 x 256, K=128) -- split-tf32 (top-k feeds on it)
    pack_wt_kernel<<<256, 128>>>(gcn_w_W);
    tgemm_kernel<1><<<dim3(2, (NSYM + 1 + 127) / 128), 256, SM2>>>(
        sym, 128, pWt, 128, pP, 256, NSYM + 1, 256, 128, nullptr, nullptr, 0, 0);

    // 2) neighbor encoder -> g_qvec, g_svec
    neighbor_kernel<<<8202, 128>>>(query, support, q_l1, q_deg_l, q_r1, q_deg_r,
                                   s_l1, s_deg_l, s_r1, s_deg_r,
                                   sym, gcn_w_b, gcn_b, gate_w, gate_temp);

    // 3) support encoder -> g_sg, g_sgn
    se1_kernel<<<(FEW * 512 + 7) / 8, 256>>>(se_W1, se_b1);
    se2_kernel<<<(FEW * 256 + 7) / 8, 256>>>(se_W2, se_b2);
    se3_kernel<<<1, 256>>>(ln_g, ln_b);

    // 4) LSTM weight packing + constants
    prep_lstm_kernel<<<1024, 256>>>(lstm_Wih, lstm_Whh, lstm_bih, lstm_bhh);

    // 5) query support-encoder + LN  (tf32)
    tgemm_kernel<0><<<dim3(4, 32), 256, SM1>>>(pQv, 256, se_W1, 256, pH1, 512,
                                               B, 512, 256, se_b1, nullptr, 0, 1);
    tgemm_kernel<0><<<dim3(2, 32), 256, SM1>>>(pH1, 512, se_W2, 512, pTmp, 256,
                                               B, 256, 512, se_b2, pQv, 256, 0);
    ln_kernel<<<B, 256>>>(ln_g, ln_b);

    // 6) Gq = X @ Wihp^T + (bih+bhh)  (tf32)
    tgemm_kernel<0><<<dim3(8, 32), 256, SM1>>>(pX, 256, pWihp, 256, pGq, 1024,
                                               B, 1024, 256, pBsum, nullptr, 0, 0);

    // 7) LSTM steps
    lstm_elem_kernel<<<B, 256>>>(pGq, 1);
    for (int s = 1; s < 4; s++) {
        tgemm_kernel<0><<<dim3(8, 32), 256, SM1>>>(pH, 256, pWhhLp, 256, pGates, 1024,
                                                   B, 1024, 256, pWhhr, pGq, 1024, 0);
        lstm_elem_kernel<<<B, 256>>>(pGates, 0);
    }

    // 8) final cosine
    final_kernel<<<B / 8, 256>>>(out);
}

// round 4
// speedup vs baseline: 3.3311x; 1.1818x over previous
#include <cuda_runtime.h>
#include <cuda_bf16.h>
#include <math.h>
#include <stdint.h>

// ---------------------------------------------------------------------------
// Problem constants
// ---------------------------------------------------------------------------
#define NSYM   100000
#define PADID  100000
#define B      4096
#define FEW    5
#define MAXK   50
#define KNEI   10
#define EPS    1e-8f
#define LNEPS  1e-5f

// ---------------------------------------------------------------------------
// Scratch (device globals -- no allocations allowed)
// ---------------------------------------------------------------------------
__device__ __align__(128) float g_P[(NSYM + 1) * 256];
__device__ __align__(128) float g_Wt[256 * 128];
__device__ __align__(128) float g_qvec[B * 256];
__device__ __align__(128) float g_svec[FEW * 256];
__device__ __align__(128) float g_sh1[FEW * 512];
__device__ __align__(128) float g_sh[FEW * 256];
__device__ __align__(128) float g_sg[256];
__device__ __align__(128) float g_sgn[1];
__device__ __align__(128) float g_H1[B * 512];
__device__ __align__(128) float g_tmp[B * 256];
__device__ __align__(128) float g_X[B * 256];
__device__ __align__(128) float g_Wihp[1024 * 256];
__device__ __align__(128) float g_WhhLp[1024 * 256];
__device__ __align__(128) float g_bsum[1024];
__device__ __align__(128) float g_whhr[1024];
__device__ __align__(128) float g_Gq[B * 1024];
__device__ __align__(128) float g_c[B * 256];
__device__ __align__(128) float g_h[B * 256];
__device__ __align__(128) float g_h2[B * 256];

__device__ __forceinline__ float sigf(float x) { return 1.f / (1.f + expf(-x)); }

__device__ __forceinline__ uint32_t f2tf32(float x) {
    uint32_t r;
    asm("cvt.rna.tf32.f32 %0, %1;" : "=r"(r) : "f"(x));
    return r;
}

#define MMA_TF32(d, a, b)                                                     \
    asm volatile("mma.sync.aligned.m16n8k8.row.col.f32.tf32.tf32.f32 "        \
                 "{%0,%1,%2,%3}, {%4,%5,%6,%7}, {%8,%9}, {%0,%1,%2,%3};"      \
                 : "+f"(d[0]), "+f"(d[1]), "+f"(d[2]), "+f"(d[3])             \
                 : "r"(a[0]), "r"(a[1]), "r"(a[2]), "r"(a[3]),                \
                   "r"(b[0]), "r"(b[1]))

#define MMA_BF16(d, a, b)                                                     \
    asm volatile("mma.sync.aligned.m16n8k16.row.col.f32.bf16.bf16.f32 "       \
                 "{%0,%1,%2,%3}, {%4,%5,%6,%7}, {%8,%9}, {%0,%1,%2,%3};"      \
                 : "+f"(d[0]), "+f"(d[1]), "+f"(d[2]), "+f"(d[3])             \
                 : "r"(a[0]), "r"(a[1]), "r"(a[2]), "r"(a[3]),                \
                   "r"(b[0]), "r"(b[1]))

// ---------------------------------------------------------------------------
// TF32 tensor-core GEMM: C[M,N] = A[M,K] @ B[N,K]^T (+bias[n]) (+res) (relu?)
// BM=BN=128, BK=32, 256 threads (8 warps, 2x4), warp tile 64x32.
// EPI=0: generic. EPI=1: LSTM first step (write gates to C, compute h/c, c0=0).
// EPI=2: LSTM later step (res=Gq add, compute h/c only; no C write).
// For EPI!=0, gate rows are interleaved: column = 4*unit + gate{i,f,g,o}.
// ---------------------------------------------------------------------------
#define SMS 36
template <int EPI>
__global__ __launch_bounds__(256) void tgemm_kernel(
    const float* __restrict__ A, int lda,
    const float* __restrict__ Bm, int ldb,
    float* __restrict__ C, int ldc,
    int M, int N, int K,
    const float* __restrict__ bias,
    const float* __restrict__ res, int ldres,
    int relu,
    float* __restrict__ hout)
{
    extern __shared__ float sm[];
    float* sAh = sm;
    float* sBh = sm + 128 * SMS;

    const int tid = threadIdx.x;
    const int bm = blockIdx.y * 128;
    const int bn = blockIdx.x * 128;
    const int wid = tid >> 5, lane = tid & 31;
    const int wm = (wid >> 2) * 64, wn = (wid & 3) * 32;
    const int gr = lane >> 2, gc = lane & 3;
    const int lrow = tid >> 3;
    const int lcol = (tid & 7) * 4;

    float acc[4][4][4];
#pragma unroll
    for (int i = 0; i < 4; i++)
#pragma unroll
        for (int j = 0; j < 4; j++)
#pragma unroll
            for (int k = 0; k < 4; k++) acc[i][j][k] = 0.f;

    for (int k0 = 0; k0 < K; k0 += 32) {
#pragma unroll
        for (int p = 0; p < 4; p++) {
            int row = p * 32 + lrow;
            int ga = bm + row;
            float4 va = (ga < M) ? *(const float4*)(A + (size_t)ga * lda + k0 + lcol)
                                 : make_float4(0.f, 0.f, 0.f, 0.f);
            float4 vb = *(const float4*)(Bm + (size_t)(bn + row) * ldb + k0 + lcol);
            float av[4] = {va.x, va.y, va.z, va.w};
            float bv[4] = {vb.x, vb.y, vb.z, vb.w};
#pragma unroll
            for (int i = 0; i < 4; i++) {
                sAh[row * SMS + lcol + i] = __uint_as_float(f2tf32(av[i]));
                sBh[row * SMS + lcol + i] = __uint_as_float(f2tf32(bv[i]));
            }
        }
        __syncthreads();

#pragma unroll
        for (int ks = 0; ks < 4; ks++) {
            int kb = ks * 8;
            uint32_t ah[4][4], bh[4][2];
#pragma unroll
            for (int mi = 0; mi < 4; mi++) {
                int base = (wm + mi * 16 + gr) * SMS + kb + gc;
                ah[mi][0] = __float_as_uint(sAh[base]);
                ah[mi][1] = __float_as_uint(sAh[base + 8 * SMS]);
                ah[mi][2] = __float_as_uint(sAh[base + 4]);
                ah[mi][3] = __float_as_uint(sAh[base + 8 * SMS + 4]);
            }
#pragma unroll
            for (int ni = 0; ni < 4; ni++) {
                int base = (wn + ni * 8 + gr) * SMS + kb + gc;
                bh[ni][0] = __float_as_uint(sBh[base]);
                bh[ni][1] = __float_as_uint(sBh[base + 4]);
            }
#pragma unroll
            for (int mi = 0; mi < 4; mi++)
#pragma unroll
                for (int ni = 0; ni < 4; ni++)
                    MMA_TF32(acc[mi][ni], ah[mi], bh[ni]);
        }
        __syncthreads();
    }

    // Epilogue
#pragma unroll
    for (int mi = 0; mi < 4; mi++) {
#pragma unroll
        for (int ni = 0; ni < 4; ni++) {
            int col = bn + wn + ni * 8 + gc * 2;
            float b0 = bias ? bias[col] : 0.f;
            float b1 = bias ? bias[col + 1] : 0.f;
            float v[4];
#pragma unroll
            for (int half = 0; half < 2; half++) {
                int r = bm + wm + mi * 16 + gr + half * 8;
                float x0 = acc[mi][ni][half * 2 + 0] + b0;
                float x1 = acc[mi][ni][half * 2 + 1] + b1;
                if (res && r < M) {
                    x0 += res[(size_t)r * ldres + col];
                    x1 += res[(size_t)r * ldres + col + 1];
                }
                if (EPI == 0) {
                    if (r < M) {
                        float y0 = relu ? fmaxf(x0, 0.f) : x0;
                        float y1 = relu ? fmaxf(x1, 0.f) : x1;
                        C[(size_t)r * ldc + col]     = y0;
                        C[(size_t)r * ldc + col + 1] = y1;
                    }
                } else if (EPI == 1) {
                    C[(size_t)r * ldc + col]     = x0;
                    C[(size_t)r * ldc + col + 1] = x1;
                }
                v[half * 2 + 0] = x0;
                v[half * 2 + 1] = x1;
            }
            if (EPI != 0) {
                float p0 = __shfl_xor_sync(~0u, v[0], 1);
                float p1 = __shfl_xor_sync(~0u, v[1], 1);
                float p2 = __shfl_xor_sync(~0u, v[2], 1);
                float p3 = __shfl_xor_sync(~0u, v[3], 1);
                if (!(gc & 1)) {
                    int u = col >> 2;
#pragma unroll
                    for (int half = 0; half < 2; half++) {
                        int r = bm + wm + mi * 16 + gr + half * 8;
                        float gi = v[half * 2], gf = v[half * 2 + 1];
                        float gg = half ? p2 : p0;
                        float go = half ? p3 : p1;
                        float cp = (EPI == 1) ? 0.f : g_c[(size_t)r * 256 + u];
                        float cn = sigf(gf) * cp + sigf(gi) * tanhf(gg);
                        g_c[(size_t)r * 256 + u] = cn;
                        hout[(size_t)r * 256 + u] =
                            g_X[(size_t)r * 256 + u] + sigf(go) * tanhf(cn);
                    }
                }
            }
        }
    }
}

// ---------------------------------------------------------------------------
// bf16x3 GEMM for the P table: C = A @ B^T, near-fp32 accuracy (~1e-5 rel).
// BM=BN=128, BK=32, m16n8k16. Same warp layout as tgemm.
// ---------------------------------------------------------------------------
#define BSMS 20
__device__ __forceinline__ void packbf(float f0, float f1, uint32_t& hi, uint32_t& lo)
{
    __nv_bfloat162 h = __floats2bfloat162_rn(f0, f1);   // .x=f0(lo half), .y=f1
    float r0 = __bfloat162float(h.x), r1 = __bfloat162float(h.y);
    __nv_bfloat162 l = __floats2bfloat162_rn(f0 - r0, f1 - r1);
    hi = *reinterpret_cast<uint32_t*>(&h);
    lo = *reinterpret_cast<uint32_t*>(&l);
}

__global__ __launch_bounds__(256) void bgemm_kernel(
    const float* __restrict__ A, int lda,
    const float* __restrict__ Bm, int ldb,
    float* __restrict__ C, int ldc,
    int M, int N, int K)
{
    extern __shared__ uint32_t smu[];
    uint32_t* sAh = smu;
    uint32_t* sAl = smu + 128 * BSMS;
    uint32_t* sBh = smu + 2 * 128 * BSMS;
    uint32_t* sBl = smu + 3 * 128 * BSMS;

    const int tid = threadIdx.x;
    const int bm = blockIdx.y * 128;
    const int bn = blockIdx.x * 128;
    const int wid = tid >> 5, lane = tid & 31;
    const int wm = (wid >> 2) * 64, wn = (wid & 3) * 32;
    const int gr = lane >> 2, gc = lane & 3;
    const int lrow = tid >> 3;
    const int kp0 = (tid & 7) * 2;          // kpair base; float col = kp0*2

    float acc[4][4][4];
#pragma unroll
    for (int i = 0; i < 4; i++)
#pragma unroll
        for (int j = 0; j < 4; j++)
#pragma unroll
            for (int k = 0; k < 4; k++) acc[i][j][k] = 0.f;

    for (int k0 = 0; k0 < K; k0 += 32) {
#pragma unroll
        for (int p = 0; p < 4; p++) {
            int row = p * 32 + lrow;
            int ga = bm + row;
            float4 va = (ga < M) ? *(const float4*)(A + (size_t)ga * lda + k0 + kp0 * 2)
                                 : make_float4(0.f, 0.f, 0.f, 0.f);
            float4 vb = *(const float4*)(Bm + (size_t)(bn + row) * ldb + k0 + kp0 * 2);
            uint32_t h, l;
            packbf(va.x, va.y, h, l); sAh[row * BSMS + kp0] = h;     sAl[row * BSMS + kp0] = l;
            packbf(va.z, va.w, h, l); sAh[row * BSMS + kp0 + 1] = h; sAl[row * BSMS + kp0 + 1] = l;
            packbf(vb.x, vb.y, h, l); sBh[row * BSMS + kp0] = h;     sBl[row * BSMS + kp0] = l;
            packbf(vb.z, vb.w, h, l); sBh[row * BSMS + kp0 + 1] = h; sBl[row * BSMS + kp0 + 1] = l;
        }
        __syncthreads();

#pragma unroll
        for (int kb = 0; kb < 2; kb++) {
            uint32_t ah[4][4], al[4][4], bh[4][2], bl[4][2];
#pragma unroll
            for (int mi = 0; mi < 4; mi++) {
                int base = (wm + mi * 16 + gr) * BSMS + kb * 8 + gc;
                ah[mi][0] = sAh[base];
                ah[mi][1] = sAh[base + 8 * BSMS];
                ah[mi][2] = sAh[base + 4];
                ah[mi][3] = sAh[base + 8 * BSMS + 4];
                al[mi][0] = sAl[base];
                al[mi][1] = sAl[base + 8 * BSMS];
                al[mi][2] = sAl[base + 4];
                al[mi][3] = sAl[base + 8 * BSMS + 4];
            }
#pragma unroll
            for (int ni = 0; ni < 4; ni++) {
                int base = (wn + ni * 8 + gr) * BSMS + kb * 8 + gc;
                bh[ni][0] = sBh[base];
                bh[ni][1] = sBh[base + 4];
                bl[ni][0] = sBl[base];
                bl[ni][1] = sBl[base + 4];
            }
#pragma unroll
            for (int mi = 0; mi < 4; mi++)
#pragma unroll
                for (int ni = 0; ni < 4; ni++) {
                    MMA_BF16(acc[mi][ni], ah[mi], bh[ni]);
                    MMA_BF16(acc[mi][ni], ah[mi], bl[ni]);
                    MMA_BF16(acc[mi][ni], al[mi], bh[ni]);
                }
        }
        __syncthreads();
    }

#pragma unroll
    for (int mi = 0; mi < 4; mi++)
#pragma unroll
        for (int ni = 0; ni < 4; ni++) {
            int col = bn + wn + ni * 8 + gc * 2;
#pragma unroll
            for (int half = 0; half < 2; half++) {
                int r = bm + wm + mi * 16 + gr + half * 8;
                if (r < M) {
                    C[(size_t)r * ldc + col]     = acc[mi][ni][half * 2 + 0];
                    C[(size_t)r * ldc + col + 1] = acc[mi][ni][half * 2 + 1];
                }
            }
        }
}

// ---------------------------------------------------------------------------
// Rearrange gcn_w_W (128 x 256) into Wt (256 x 128)
// ---------------------------------------------------------------------------
__global__ void pack_wt_kernel(const float* __restrict__ W)
{
    int n = blockIdx.x, k = threadIdx.x;
    g_Wt[n * 128 + k] = W[(n & 127) * 256 + ((n >> 7) << 7) + k];
}

// ---------------------------------------------------------------------------
// Neighbor encoder: one block (128 thr) per entity. 8202 entities.
// ---------------------------------------------------------------------------
__global__ void neighbor_kernel(const int* __restrict__ query,
                                const int* __restrict__ support,
                                const int* __restrict__ q_l1, const int* __restrict__ q_deg_l,
                                const int* __restrict__ q_r1, const int* __restrict__ q_deg_r,
                                const int* __restrict__ s_l1, const int* __restrict__ s_deg_l,
                                const int* __restrict__ s_r1, const int* __restrict__ s_deg_r,
                                const float* __restrict__ sym,
                                const float* __restrict__ gwb, const float* __restrict__ gb,
                                const float* __restrict__ gate_w,
                                const float* __restrict__ gate_temp)
{
    __shared__ float s_self[128], s_bias[128];
    __shared__ float s_proj[MAXK][128];
    __shared__ float s_cos[MAXK];
    __shared__ float s_gw[MAXK];
    __shared__ int   s_sel[KNEI];
    __shared__ float s_scal[2];

    int e = blockIdx.x;
    const int* conn; int sid, deg; float* outp;
    if (e < 4096)      { conn = q_l1 + e * 100;                sid = query[e * 2];           deg = q_deg_l[e];      outp = g_qvec + e * 256; }
    else if (e < 8192) { int i = e - 4096; conn = q_r1 + i * 100; sid = query[i * 2 + 1];   deg = q_deg_r[i];      outp = g_qvec + i * 256 + 128; }
    else if (e < 8197) { int i = e - 8192; conn = s_l1 + i * 100; sid = support[i * 2];     deg = s_deg_l[i];      outp = g_svec + i * 256; }
    else               { int i = e - 8197; conn = s_r1 + i * 100; sid = support[i * 2 + 1]; deg = s_deg_r[i];      outp = g_svec + i * 256 + 128; }

    int t = threadIdx.x, lane = t & 31, w = t >> 5;
    s_self[t] = sym[(size_t)sid * 128 + t];
    s_bias[t] = gwb[t] + gb[t];
    if (t < MAXK) { int r = conn[2 * t]; s_gw[t] = gate_w[(r == PADID) ? 0 : r]; }
    __syncthreads();

    if (w == 0) {
        float ss = 0.f;
#pragma unroll
        for (int i = 0; i < 4; i++) { float v = s_self[lane + 32 * i]; ss += v * v; }
        for (int o = 16; o > 0; o >>= 1) ss += __shfl_xor_sync(~0u, ss, o);
        if (lane == 0) s_scal[0] = sqrtf(ss + EPS);
    }
    __syncthreads();
    float nself = s_scal[0];

    for (int base = 0; base < 52; base += 4) {
        int n = base + w;
        if (n < MAXK) {
            int rel = conn[2 * n], ent = conn[2 * n + 1];
            const float* pr = g_P + (size_t)rel * 256;
            const float* pe = g_P + (size_t)ent * 256 + 128;
            float dp = 0.f, nn = 0.f;
#pragma unroll
            for (int i = 0; i < 4; i++) {
                int d = lane + 32 * i;
                float v = pr[d] + pe[d] + s_bias[d];
                v = (v > 0.f) ? v : 0.01f * v;
                if (rel == PADID) v = 0.f;
                s_proj[n][d] = v;
                dp += s_self[d] * v;
                nn += v * v;
            }
            for (int o = 16; o > 0; o >>= 1) {
                dp += __shfl_xor_sync(~0u, dp, o);
                nn += __shfl_xor_sync(~0u, nn, o);
            }
            if (lane == 0) {
                float nnei = sqrtf(nn + EPS);
                s_cos[n] = dp / (nself * nnei + EPS);
            }
        }
    }
    __syncthreads();

    if (w == 0) {
        // parallel top-K: lane owns candidates lane, lane+32
        float v0 = s_cos[lane];
        float v1 = (lane + 32 < MAXK) ? s_cos[lane + 32] : -3.0e38f;
#pragma unroll
        for (int k = 0; k < KNEI; k++) {
            float bv = v0; int bi = lane;
            if (v1 > bv) { bv = v1; bi = lane + 32; }
            for (int o = 16; o > 0; o >>= 1) {
                float ov = __shfl_xor_sync(~0u, bv, o);
                int   oi = __shfl_xor_sync(~0u, bi, o);
                if (ov > bv || (ov == bv && oi < bi)) { bv = ov; bi = oi; }
            }
            if (lane == 0) s_sel[k] = bi;
            if (bi == lane) v0 = -3.0e38f;
            else if (bi == lane + 32) v1 = -3.0e38f;
        }
    } else if (w == 1) {
        float gv = s_gw[lane];
        gv += (lane + 32 < MAXK) ? s_gw[lane + 32] : 0.f;
        for (int o = 16; o > 0; o >>= 1) gv += __shfl_xor_sync(~0u, gv, o);
        if (lane == 0) {
            float gate = sigf((gv / 50.f) / gate_temp[0]);
            if (deg <= 0) gate = 1.f;
            s_scal[1] = gate;
        }
    }
    __syncthreads();

    float agg = 0.f;
#pragma unroll
    for (int k = 0; k < KNEI; k++) agg += s_proj[s_sel[k]][t];
    agg /= 10.f;
    outp[t] = tanhf(s_self[t] + s_scal[1] * agg);
}

// ---------------------------------------------------------------------------
// Support encoder stages
// ---------------------------------------------------------------------------
__global__ void se1_kernel(const float* __restrict__ W1, const float* __restrict__ b1)
{
    int gw = (blockIdx.x * blockDim.x + threadIdx.x) >> 5;
    int lane = threadIdx.x & 31;
    if (gw >= FEW * 512) return;
    int r = gw >> 9, j = gw & 511;
    const float4* x = (const float4*)(g_svec + r * 256);
    const float4* w = (const float4*)(W1 + (size_t)j * 256);
    float acc = 0.f;
#pragma unroll
    for (int k = lane; k < 64; k += 32) {
        float4 xv = x[k], wv = w[k];
        acc = fmaf(xv.x, wv.x, acc); acc = fmaf(xv.y, wv.y, acc);
        acc = fmaf(xv.z, wv.z, acc); acc = fmaf(xv.w, wv.w, acc);
    }
    for (int o = 16; o > 0; o >>= 1) acc += __shfl_xor_sync(~0u, acc, o);
    if (lane == 0) g_sh1[r * 512 + j] = fmaxf(acc + b1[j], 0.f);
}

__global__ void se2_kernel(const float* __restrict__ W2, const float* __restrict__ b2)
{
    int gw = (blockIdx.x * blockDim.x + threadIdx.x) >> 5;
    int lane = threadIdx.x & 31;
    if (gw >= FEW * 256) return;
    int r = gw >> 8, c = gw & 255;
    const float4* x = (const float4*)(g_sh1 + r * 512);
    const float4* w = (const float4*)(W2 + (size_t)c * 512);
    float acc = 0.f;
#pragma unroll
    for (int k = lane; k < 128; k += 32) {
        float4 xv = x[k], wv = w[k];
        acc = fmaf(xv.x, wv.x, acc); acc = fmaf(xv.y, wv.y, acc);
        acc = fmaf(xv.z, wv.z, acc); acc = fmaf(xv.w, wv.w, acc);
    }
    for (int o = 16; o > 0; o >>= 1) acc += __shfl_xor_sync(~0u, acc, o);
    if (lane == 0) g_sh[r * 256 + c] = acc + b2[c] + g_svec[r * 256 + c];
}

__global__ void se3_kernel(const float* __restrict__ g, const float* __restrict__ b)
{
    __shared__ float smu[FEW], srs[FEW];
    __shared__ float red[8];
    int t = threadIdx.x, lane = t & 31, w = t >> 5;

    if (w < FEW) {
        const float* row = g_sh + w * 256;
        float s = 0.f;
#pragma unroll
        for (int i = 0; i < 8; i++) s += row[lane + 32 * i];
        for (int o = 16; o > 0; o >>= 1) s += __shfl_xor_sync(~0u, s, o);
        float mu = s / 256.f;
        float q = 0.f;
#pragma unroll
        for (int i = 0; i < 8; i++) { float d = row[lane + 32 * i] - mu; q += d * d; }
        for (int o = 16; o > 0; o >>= 1) q += __shfl_xor_sync(~0u, q, o);
        if (lane == 0) { smu[w] = mu; srs[w] = 1.f / sqrtf(q / 256.f + LNEPS); }
    }
    __syncthreads();

    float acc = 0.f;
#pragma unroll
    for (int r = 0; r < FEW; r++)
        acc += g[t] * (g_sh[r * 256 + t] - smu[r]) * srs[r] + b[t];
    acc *= 0.2f;
    g_sg[t] = acc;

    float nq = acc * acc;
    for (int o = 16; o > 0; o >>= 1) nq += __shfl_xor_sync(~0u, nq, o);
    if (lane == 0) red[w] = nq;
    __syncthreads();
    if (t == 0) {
        float s = 0.f;
        for (int i = 0; i < 8; i++) s += red[i];
        g_sgn[0] = sqrtf(s + EPS);
    }
}

// ---------------------------------------------------------------------------
// LSTM prep: interleaved packing, packed row j = 4*unit + gate.
// Source row jm = gate*512 + unit (gate order i,f,g,o).
// ---------------------------------------------------------------------------
__global__ void prep_lstm_kernel(const float* __restrict__ Wih, const float* __restrict__ Whh,
                                 const float* __restrict__ bih, const float* __restrict__ bhh)
{
    int j = blockIdx.x;
    int u = j >> 2, gidx = j & 3;
    int jm = gidx * 512 + u;
    int t = threadIdx.x;
    g_Wihp[j * 256 + t]  = Wih[jm * 256 + t];
    g_WhhLp[j * 256 + t] = Whh[jm * 512 + t];
    float p = g_sg[t] * Whh[jm * 512 + 256 + t];
    __shared__ float red[8];
    for (int o = 16; o > 0; o >>= 1) p += __shfl_xor_sync(~0u, p, o);
    if ((t & 31) == 0) red[t >> 5] = p;
    __syncthreads();
    if (t == 0) {
        float s = 0.f;
        for (int i = 0; i < 8; i++) s += red[i];
        g_whhr[j] = s;
        g_bsum[j] = bih[jm] + bhh[jm];
    }
}

// ---------------------------------------------------------------------------
// LayerNorm rows of g_tmp -> g_X
// ---------------------------------------------------------------------------
__global__ void ln_kernel(const float* __restrict__ g, const float* __restrict__ b)
{
    int row = blockIdx.x, t = threadIdx.x;
    float v = g_tmp[(size_t)row * 256 + t];
    __shared__ float red[8];
    __shared__ float s_mu, s_rs;
    float s = v;
    for (int o = 16; o > 0; o >>= 1) s += __shfl_xor_sync(~0u, s, o);
    if ((t & 31) == 0) red[t >> 5] = s;
    __syncthreads();
    if (t == 0) { float m = 0.f; for (int i = 0; i < 8; i++) m += red[i]; s_mu = m / 256.f; }
    __syncthreads();
    float d = v - s_mu;
    float q = d * d;
    for (int o = 16; o > 0; o >>= 1) q += __shfl_xor_sync(~0u, q, o);
    if ((t & 31) == 0) red[t >> 5] = q;
    __syncthreads();
    if (t == 0) { float m = 0.f; for (int i = 0; i < 8; i++) m += red[i]; s_rs = 1.f / sqrtf(m / 256.f + LNEPS); }
    __syncthreads();
    g_X[(size_t)row * 256 + t] = g[t] * d * s_rs + b[t];
}

// ---------------------------------------------------------------------------
// Final cosine vs support_g
// ---------------------------------------------------------------------------
__global__ void final_kernel(const float* __restrict__ h_in, float* __restrict__ out)
{
    __shared__ float ssg[256];
    int t = threadIdx.x, lane = t & 31, w = t >> 5;
    ssg[t] = g_sg[t];
    __syncthreads();
    int row = blockIdx.x * 8 + w;
    const float* h = h_in + (size_t)row * 256;
    float dp = 0.f, nq = 0.f;
#pragma unroll
    for (int i = 0; i < 8; i++) {
        int d = lane + 32 * i;
        float v = h[d];
        dp += v * ssg[d];
        nq += v * v;
    }
    for (int o = 16; o > 0; o >>= 1) {
        dp += __shfl_xor_sync(~0u, dp, o);
        nq += __shfl_xor_sync(~0u, nq, o);
    }
    if (lane == 0) out[row] = dp / (sqrtf(nq + EPS) * g_sgn[0]);
}

// ---------------------------------------------------------------------------
// kernel_launch
// ---------------------------------------------------------------------------
extern "C" void kernel_launch(void* const* d_in, const int* in_sizes, int n_in,
                              void* d_out, int out_size)
{
    const int*   query     = (const int*)d_in[0];
    const int*   support   = (const int*)d_in[1];
    const int*   q_l1      = (const int*)d_in[2];
    const int*   q_deg_l   = (const int*)d_in[3];
    const int*   q_r1      = (const int*)d_in[4];
    const int*   q_deg_r   = (const int*)d_in[5];
    const int*   s_l1      = (const int*)d_in[6];
    const int*   s_deg_l   = (const int*)d_in[7];
    const int*   s_r1      = (const int*)d_in[8];
    const int*   s_deg_r   = (const int*)d_in[9];
    const float* sym       = (const float*)d_in[10];
    const float* gcn_w_W   = (const float*)d_in[11];
    const float* gcn_w_b   = (const float*)d_in[12];
    const float* gcn_b     = (const float*)d_in[13];
    const float* gate_w    = (const float*)d_in[14];
    const float* gate_temp = (const float*)d_in[15];
    const float* se_W1     = (const float*)d_in[16];
    const float* se_b1     = (const float*)d_in[17];
    const float* se_W2     = (const float*)d_in[18];
    const float* se_b2     = (const float*)d_in[19];
    const float* ln_g      = (const float*)d_in[20];
    const float* ln_b      = (const float*)d_in[21];
    const float* lstm_Wih  = (const float*)d_in[22];
    const float* lstm_Whh  = (const float*)d_in[23];
    const float* lstm_bih  = (const float*)d_in[24];
    const float* lstm_bhh  = (const float*)d_in[25];
    float* out = (float*)d_out;

    float *pP, *pWt, *pQv, *pH1, *pTmp, *pX, *pWihp, *pWhhLp, *pBsum, *pWhhr, *pGq, *pH, *pH2;
    cudaGetSymbolAddress((void**)&pP,     g_P);
    cudaGetSymbolAddress((void**)&pWt,    g_Wt);
    cudaGetSymbolAddress((void**)&pQv,    g_qvec);
    cudaGetSymbolAddress((void**)&pH1,    g_H1);
    cudaGetSymbolAddress((void**)&pTmp,   g_tmp);
    cudaGetSymbolAddress((void**)&pX,     g_X);
    cudaGetSymbolAddress((void**)&pWihp,  g_Wihp);
    cudaGetSymbolAddress((void**)&pWhhLp, g_WhhLp);
    cudaGetSymbolAddress((void**)&pBsum,  g_bsum);
    cudaGetSymbolAddress((void**)&pWhhr,  g_whhr);
    cudaGetSymbolAddress((void**)&pGq,    g_Gq);
    cudaGetSymbolAddress((void**)&pH,     g_h);
    cudaGetSymbolAddress((void**)&pH2,    g_h2);

    const int SM_T = 2 * 128 * SMS * (int)sizeof(float);     // 36864
    const int SM_B = 4 * 128 * BSMS * (int)sizeof(uint32_t); // 40960
    static int attr_done = 0;
    if (!attr_done) {
        cudaFuncSetAttribute(tgemm_kernel<0>, cudaFuncAttributeMaxDynamicSharedMemorySize, SM_T);
        cudaFuncSetAttribute(tgemm_kernel<1>, cudaFuncAttributeMaxDynamicSharedMemorySize, SM_T);
        cudaFuncSetAttribute(tgemm_kernel<2>, cudaFuncAttributeMaxDynamicSharedMemorySize, SM_T);
        cudaFuncSetAttribute(bgemm_kernel,    cudaFuncAttributeMaxDynamicSharedMemorySize, SM_B);
        attr_done = 1;
    }

    // 1) P = sym_emb @ Wt^T  (100001 x 256, K=128) -- bf16x3
    pack_wt_kernel<<<256, 128>>>(gcn_w_W);
    bgemm_kernel<<<dim3(2, (NSYM + 1 + 127) / 128), 256, SM_B>>>(
        sym, 128, pWt, 128, pP, 256, NSYM + 1, 256, 128);

    // 2) neighbor encoder -> g_qvec, g_svec
    neighbor_kernel<<<8202, 128>>>(query, support, q_l1, q_deg_l, q_r1, q_deg_r,
                                   s_l1, s_deg_l, s_r1, s_deg_r,
                                   sym, gcn_w_b, gcn_b, gate_w, gate_temp);

    // 3) support encoder -> g_sg, g_sgn
    se1_kernel<<<(FEW * 512 + 7) / 8, 256>>>(se_W1, se_b1);
    se2_kernel<<<(FEW * 256 + 7) / 8, 256>>>(se_W2, se_b2);
    se3_kernel<<<1, 256>>>(ln_g, ln_b);

    // 4) LSTM weight packing (interleaved) + constants
    prep_lstm_kernel<<<1024, 256>>>(lstm_Wih, lstm_Whh, lstm_bih, lstm_bhh);

    // 5) query support-encoder + LN  (tf32)
    tgemm_kernel<0><<<dim3(4, 32), 256, SM_T>>>(pQv, 256, se_W1, 256, pH1, 512,
                                                B, 512, 256, se_b1, nullptr, 0, 1, nullptr);
    tgemm_kernel<0><<<dim3(2, 32), 256, SM_T>>>(pH1, 512, se_W2, 512, pTmp, 256,
                                                B, 256, 512, se_b2, pQv, 256, 0, nullptr);
    ln_kernel<<<B, 256>>>(ln_g, ln_b);

    // 6) Gq = X @ Wihp^T + bsum; fused LSTM step 1 (c0=0) -> h in g_h
    tgemm_kernel<1><<<dim3(8, 32), 256, SM_T>>>(pX, 256, pWihp, 256, pGq, 1024,
                                                B, 1024, 256, pBsum, nullptr, 0, 0, pH);

    // 7) LSTM steps 2..4: gates = h@WhhL^T + whhr + Gq; fused elementwise.
    //    Double-buffer h to avoid read/write races across column-blocks.
    tgemm_kernel<2><<<dim3(8, 32), 256, SM_T>>>(pH, 256, pWhhLp, 256, nullptr, 0,
                                                B, 1024, 256, pWhhr, pGq, 1024, 0, pH2);
    tgemm_kernel<2><<<dim3(8, 32), 256, SM_T>>>(pH2, 256, pWhhLp, 256, nullptr, 0,
                                                B, 1024, 256, pWhhr, pGq, 1024, 0, pH);
    tgemm_kernel<2><<<dim3(8, 32), 256, SM_T>>>(pH, 256, pWhhLp, 256, nullptr, 0,
                                                B, 1024, 256, pWhhr, pGq, 1024, 0, pH2);

    // 8) final cosine (h after 4 steps = g_h2)
    final_kernel<<<B / 8, 256>>>(pH2, out);
}

// round 5
// speedup vs baseline: 3.7986x; 1.1404x over previous
#include <cuda_runtime.h>
#include <cuda_bf16.h>
#include <math.h>
#include <stdint.h>

// ---------------------------------------------------------------------------
// Problem constants
// ---------------------------------------------------------------------------
#define NSYM   100000
#define PADID  100000
#define B      4096
#define FEW    5
#define MAXK   50
#define KNEI   10
#define EPS    1e-8f
#define LNEPS  1e-5f

// ---------------------------------------------------------------------------
// Scratch (device globals -- no allocations allowed)
// ---------------------------------------------------------------------------
__device__ __align__(128) float g_P[(NSYM + 1) * 256];
__device__ __align__(128) float g_Wt[256 * 128];
__device__ __align__(128) float g_qvec[B * 256];
__device__ __align__(128) float g_svec[FEW * 256];
__device__ __align__(128) float g_sh1[FEW * 512];
__device__ __align__(128) float g_sh[FEW * 256];
__device__ __align__(128) float g_sg[256];
__device__ __align__(128) float g_sgn[1];
__device__ __align__(128) float g_H1[B * 512];
__device__ __align__(128) float g_tmp[B * 256];
__device__ __align__(128) float g_X[B * 256];
__device__ __align__(128) float g_Wihp[1024 * 256];
__device__ __align__(128) float g_WhhLp[1024 * 256];
__device__ __align__(128) float g_bsum[1024];
__device__ __align__(128) float g_whhr[1024];
__device__ __align__(128) float g_Gq[B * 1024];
__device__ __align__(128) float g_c[B * 256];
__device__ __align__(128) float g_h[B * 256];
__device__ __align__(128) float g_h2[B * 256];

__device__ __forceinline__ float sigf(float x) { return 1.f / (1.f + expf(-x)); }

__device__ __forceinline__ uint32_t f2tf32(float x) {
    uint32_t r;
    asm("cvt.rna.tf32.f32 %0, %1;" : "=r"(r) : "f"(x));
    return r;
}

#define MMA_TF32(d, a, b)                                                     \
    asm volatile("mma.sync.aligned.m16n8k8.row.col.f32.tf32.tf32.f32 "        \
                 "{%0,%1,%2,%3}, {%4,%5,%6,%7}, {%8,%9}, {%0,%1,%2,%3};"      \
                 : "+f"(d[0]), "+f"(d[1]), "+f"(d[2]), "+f"(d[3])             \
                 : "r"(a[0]), "r"(a[1]), "r"(a[2]), "r"(a[3]),                \
                   "r"(b[0]), "r"(b[1]))

#define MMA_BF16(d, a, b)                                                     \
    asm volatile("mma.sync.aligned.m16n8k16.row.col.f32.bf16.bf16.f32 "       \
                 "{%0,%1,%2,%3}, {%4,%5,%6,%7}, {%8,%9}, {%0,%1,%2,%3};"      \
                 : "+f"(d[0]), "+f"(d[1]), "+f"(d[2]), "+f"(d[3])             \
                 : "r"(a[0]), "r"(a[1]), "r"(a[2]), "r"(a[3]),                \
                   "r"(b[0]), "r"(b[1]))

// ---------------------------------------------------------------------------
// TF32 tensor-core GEMM with register prefetch.
// C[M,N] = A[M,K] @ B[N,K]^T (+bias[n]) (+res) (relu?)
// BM=BN=128, BK=32, 256 threads (8 warps, 2x4), warp tile 64x32.
// EPI=0: generic. EPI=1: LSTM first step. EPI=2: LSTM later step.
// ---------------------------------------------------------------------------
#define SMS 36
template <int EPI>
__global__ __launch_bounds__(256) void tgemm_kernel(
    const float* __restrict__ A, int lda,
    const float* __restrict__ Bm, int ldb,
    float* __restrict__ C, int ldc,
    int M, int N, int K,
    const float* __restrict__ bias,
    const float* __restrict__ res, int ldres,
    int relu,
    float* __restrict__ hout)
{
    extern __shared__ float sm[];
    float* sAh = sm;
    float* sBh = sm + 128 * SMS;

    const int tid = threadIdx.x;
    const int bm = blockIdx.y * 128;
    const int bn = blockIdx.x * 128;
    const int wid = tid >> 5, lane = tid & 31;
    const int wm = (wid >> 2) * 64, wn = (wid & 3) * 32;
    const int gr = lane >> 2, gc = lane & 3;
    const int lrow = tid >> 3;
    const int lcol = (tid & 7) * 4;

    float acc[4][4][4];
#pragma unroll
    for (int i = 0; i < 4; i++)
#pragma unroll
        for (int j = 0; j < 4; j++)
#pragma unroll
            for (int k = 0; k < 4; k++) acc[i][j][k] = 0.f;

    float4 pva[4], pvb[4];
    const bool avalid[4] = { bm + 0 * 32 + lrow < M, bm + 1 * 32 + lrow < M,
                             bm + 2 * 32 + lrow < M, bm + 3 * 32 + lrow < M };

#pragma unroll
    for (int p = 0; p < 4; p++) {
        int row = p * 32 + lrow;
        pva[p] = avalid[p] ? *(const float4*)(A + (size_t)(bm + row) * lda + lcol)
                           : make_float4(0.f, 0.f, 0.f, 0.f);
        pvb[p] = *(const float4*)(Bm + (size_t)(bn + row) * ldb + lcol);
    }

    for (int k0 = 0; k0 < K; k0 += 32) {
#pragma unroll
        for (int p = 0; p < 4; p++) {
            int row = p * 32 + lrow;
            float av[4] = {pva[p].x, pva[p].y, pva[p].z, pva[p].w};
            float bv[4] = {pvb[p].x, pvb[p].y, pvb[p].z, pvb[p].w};
#pragma unroll
            for (int i = 0; i < 4; i++) {
                sAh[row * SMS + lcol + i] = __uint_as_float(f2tf32(av[i]));
                sBh[row * SMS + lcol + i] = __uint_as_float(f2tf32(bv[i]));
            }
        }
        __syncthreads();

        if (k0 + 32 < K) {
#pragma unroll
            for (int p = 0; p < 4; p++) {
                int row = p * 32 + lrow;
                pva[p] = avalid[p] ? *(const float4*)(A + (size_t)(bm + row) * lda + k0 + 32 + lcol)
                                   : make_float4(0.f, 0.f, 0.f, 0.f);
                pvb[p] = *(const float4*)(Bm + (size_t)(bn + row) * ldb + k0 + 32 + lcol);
            }
        }

#pragma unroll
        for (int ks = 0; ks < 4; ks++) {
            int kb = ks * 8;
            uint32_t ah[4][4], bh[4][2];
#pragma unroll
            for (int mi = 0; mi < 4; mi++) {
                int base = (wm + mi * 16 + gr) * SMS + kb + gc;
                ah[mi][0] = __float_as_uint(sAh[base]);
                ah[mi][1] = __float_as_uint(sAh[base + 8 * SMS]);
                ah[mi][2] = __float_as_uint(sAh[base + 4]);
                ah[mi][3] = __float_as_uint(sAh[base + 8 * SMS + 4]);
            }
#pragma unroll
            for (int ni = 0; ni < 4; ni++) {
                int base = (wn + ni * 8 + gr) * SMS + kb + gc;
                bh[ni][0] = __float_as_uint(sBh[base]);
                bh[ni][1] = __float_as_uint(sBh[base + 4]);
            }
#pragma unroll
            for (int mi = 0; mi < 4; mi++)
#pragma unroll
                for (int ni = 0; ni < 4; ni++)
                    MMA_TF32(acc[mi][ni], ah[mi], bh[ni]);
        }
        __syncthreads();
    }

    // Epilogue
#pragma unroll
    for (int mi = 0; mi < 4; mi++) {
#pragma unroll
        for (int ni = 0; ni < 4; ni++) {
            int col = bn + wn + ni * 8 + gc * 2;
            float b0 = bias ? bias[col] : 0.f;
            float b1 = bias ? bias[col + 1] : 0.f;
            float v[4];
#pragma unroll
            for (int half = 0; half < 2; half++) {
                int r = bm + wm + mi * 16 + gr + half * 8;
                float x0 = acc[mi][ni][half * 2 + 0] + b0;
                float x1 = acc[mi][ni][half * 2 + 1] + b1;
                if (res && r < M) {
                    x0 += res[(size_t)r * ldres + col];
                    x1 += res[(size_t)r * ldres + col + 1];
                }
                if (EPI == 0) {
                    if (r < M) {
                        float y0 = relu ? fmaxf(x0, 0.f) : x0;
                        float y1 = relu ? fmaxf(x1, 0.f) : x1;
                        C[(size_t)r * ldc + col]     = y0;
                        C[(size_t)r * ldc + col + 1] = y1;
                    }
                } else if (EPI == 1) {
                    C[(size_t)r * ldc + col]     = x0;
                    C[(size_t)r * ldc + col + 1] = x1;
                }
                v[half * 2 + 0] = x0;
                v[half * 2 + 1] = x1;
            }
            if (EPI != 0) {
                float p0 = __shfl_xor_sync(~0u, v[0], 1);
                float p1 = __shfl_xor_sync(~0u, v[1], 1);
                float p2 = __shfl_xor_sync(~0u, v[2], 1);
                float p3 = __shfl_xor_sync(~0u, v[3], 1);
                if (!(gc & 1)) {
                    int u = col >> 2;
#pragma unroll
                    for (int half = 0; half < 2; half++) {
                        int r = bm + wm + mi * 16 + gr + half * 8;
                        float gi = v[half * 2], gf = v[half * 2 + 1];
                        float gg = half ? p2 : p0;
                        float go = half ? p3 : p1;
                        float cp = (EPI == 1) ? 0.f : g_c[(size_t)r * 256 + u];
                        float cn = sigf(gf) * cp + sigf(gi) * tanhf(gg);
                        g_c[(size_t)r * 256 + u] = cn;
                        hout[(size_t)r * 256 + u] =
                            g_X[(size_t)r * 256 + u] + sigf(go) * tanhf(cn);
                    }
                }
            }
        }
    }
}

// ---------------------------------------------------------------------------
// bf16x3 GEMM for the P table (register-prefetched).
// ---------------------------------------------------------------------------
#define BSMS 20
__device__ __forceinline__ void packbf(float f0, float f1, uint32_t& hi, uint32_t& lo)
{
    __nv_bfloat162 h = __floats2bfloat162_rn(f0, f1);
    float r0 = __bfloat162float(h.x), r1 = __bfloat162float(h.y);
    __nv_bfloat162 l = __floats2bfloat162_rn(f0 - r0, f1 - r1);
    hi = *reinterpret_cast<uint32_t*>(&h);
    lo = *reinterpret_cast<uint32_t*>(&l);
}

__global__ __launch_bounds__(256) void bgemm_kernel(
    const float* __restrict__ A, int lda,
    const float* __restrict__ Bm, int ldb,
    float* __restrict__ C, int ldc,
    int M, int N, int K)
{
    extern __shared__ uint32_t smu[];
    uint32_t* sAh = smu;
    uint32_t* sAl = smu + 128 * BSMS;
    uint32_t* sBh = smu + 2 * 128 * BSMS;
    uint32_t* sBl = smu + 3 * 128 * BSMS;

    const int tid = threadIdx.x;
    const int bm = blockIdx.y * 128;
    const int bn = blockIdx.x * 128;
    const int wid = tid >> 5, lane = tid & 31;
    const int wm = (wid >> 2) * 64, wn = (wid & 3) * 32;
    const int gr = lane >> 2, gc = lane & 3;
    const int lrow = tid >> 3;
    const int kp0 = (tid & 7) * 2;

    float acc[4][4][4];
#pragma unroll
    for (int i = 0; i < 4; i++)
#pragma unroll
        for (int j = 0; j < 4; j++)
#pragma unroll
            for (int k = 0; k < 4; k++) acc[i][j][k] = 0.f;

    float4 pva[4], pvb[4];
    const bool avalid[4] = { bm + 0 * 32 + lrow < M, bm + 1 * 32 + lrow < M,
                             bm + 2 * 32 + lrow < M, bm + 3 * 32 + lrow < M };
#pragma unroll
    for (int p = 0; p < 4; p++) {
        int row = p * 32 + lrow;
        pva[p] = avalid[p] ? *(const float4*)(A + (size_t)(bm + row) * lda + kp0 * 2)
                           : make_float4(0.f, 0.f, 0.f, 0.f);
        pvb[p] = *(const float4*)(Bm + (size_t)(bn + row) * ldb + kp0 * 2);
    }

    for (int k0 = 0; k0 < K; k0 += 32) {
#pragma unroll
        for (int p = 0; p < 4; p++) {
            int row = p * 32 + lrow;
            uint32_t h, l;
            packbf(pva[p].x, pva[p].y, h, l); sAh[row * BSMS + kp0] = h;     sAl[row * BSMS + kp0] = l;
            packbf(pva[p].z, pva[p].w, h, l); sAh[row * BSMS + kp0 + 1] = h; sAl[row * BSMS + kp0 + 1] = l;
            packbf(pvb[p].x, pvb[p].y, h, l); sBh[row * BSMS + kp0] = h;     sBl[row * BSMS + kp0] = l;
            packbf(pvb[p].z, pvb[p].w, h, l); sBh[row * BSMS + kp0 + 1] = h; sBl[row * BSMS + kp0 + 1] = l;
        }
        __syncthreads();

        if (k0 + 32 < K) {
#pragma unroll
            for (int p = 0; p < 4; p++) {
                int row = p * 32 + lrow;
                pva[p] = avalid[p] ? *(const float4*)(A + (size_t)(bm + row) * lda + k0 + 32 + kp0 * 2)
                                   : make_float4(0.f, 0.f, 0.f, 0.f);
                pvb[p] = *(const float4*)(Bm + (size_t)(bn + row) * ldb + k0 + 32 + kp0 * 2);
            }
        }

#pragma unroll
        for (int kb = 0; kb < 2; kb++) {
            uint32_t ah[4][4], al[4][4], bh[4][2], bl[4][2];
#pragma unroll
            for (int mi = 0; mi < 4; mi++) {
                int base = (wm + mi * 16 + gr) * BSMS + kb * 8 + gc;
                ah[mi][0] = sAh[base];
                ah[mi][1] = sAh[base + 8 * BSMS];
                ah[mi][2] = sAh[base + 4];
                ah[mi][3] = sAh[base + 8 * BSMS + 4];
                al[mi][0] = sAl[base];
                al[mi][1] = sAl[base + 8 * BSMS];
                al[mi][2] = sAl[base + 4];
                al[mi][3] = sAl[base + 8 * BSMS + 4];
            }
#pragma unroll
            for (int ni = 0; ni < 4; ni++) {
                int base = (wn + ni * 8 + gr) * BSMS + kb * 8 + gc;
                bh[ni][0] = sBh[base];
                bh[ni][1] = sBh[base + 4];
                bl[ni][0] = sBl[base];
                bl[ni][1] = sBl[base + 4];
            }
#pragma unroll
            for (int mi = 0; mi < 4; mi++)
#pragma unroll
                for (int ni = 0; ni < 4; ni++) {
                    MMA_BF16(acc[mi][ni], ah[mi], bh[ni]);
                    MMA_BF16(acc[mi][ni], ah[mi], bl[ni]);
                    MMA_BF16(acc[mi][ni], al[mi], bh[ni]);
                }
        }
        __syncthreads();
    }

#pragma unroll
    for (int mi = 0; mi < 4; mi++)
#pragma unroll
        for (int ni = 0; ni < 4; ni++) {
            int col = bn + wn + ni * 8 + gc * 2;
#pragma unroll
            for (int half = 0; half < 2; half++) {
                int r = bm + wm + mi * 16 + gr + half * 8;
                if (r < M) {
                    C[(size_t)r * ldc + col]     = acc[mi][ni][half * 2 + 0];
                    C[(size_t)r * ldc + col + 1] = acc[mi][ni][half * 2 + 1];
                }
            }
        }
}

// ---------------------------------------------------------------------------
// Rearrange gcn_w_W (128 x 256) into Wt (256 x 128)
// ---------------------------------------------------------------------------
__global__ void pack_wt_kernel(const float* __restrict__ W)
{
    int n = blockIdx.x, k = threadIdx.x;
    g_Wt[n * 128 + k] = W[(n & 127) * 256 + ((n >> 7) << 7) + k];
}

// ---------------------------------------------------------------------------
// Neighbor encoder: one block (256 thr, 8 warps) per entity. 8202 entities.
// float4 gather path: 2 x LDG.128 per lane per neighbor.
// ---------------------------------------------------------------------------
__global__ __launch_bounds__(256) void neighbor_kernel(
                                const int* __restrict__ query,
                                const int* __restrict__ support,
                                const int* __restrict__ q_l1, const int* __restrict__ q_deg_l,
                                const int* __restrict__ q_r1, const int* __restrict__ q_deg_r,
                                const int* __restrict__ s_l1, const int* __restrict__ s_deg_l,
                                const int* __restrict__ s_r1, const int* __restrict__ s_deg_r,
                                const float* __restrict__ sym,
                                const float* __restrict__ gwb, const float* __restrict__ gb,
                                const float* __restrict__ gate_w,
                                const float* __restrict__ gate_temp)
{
    __shared__ __align__(16) float s_self[128], s_bias[128];
    __shared__ __align__(16) float s_proj[MAXK][128];
    __shared__ float s_cos[MAXK];
    __shared__ float s_gw[MAXK];
    __shared__ int   s_sel[KNEI];
    __shared__ float s_scal[2];

    int e = blockIdx.x;
    const int* conn; int sid, deg; float* outp;
    if (e < 4096)      { conn = q_l1 + e * 100;                sid = query[e * 2];           deg = q_deg_l[e];      outp = g_qvec + e * 256; }
    else if (e < 8192) { int i = e - 4096; conn = q_r1 + i * 100; sid = query[i * 2 + 1];   deg = q_deg_r[i];      outp = g_qvec + i * 256 + 128; }
    else if (e < 8197) { int i = e - 8192; conn = s_l1 + i * 100; sid = support[i * 2];     deg = s_deg_l[i];      outp = g_svec + i * 256; }
    else               { int i = e - 8197; conn = s_r1 + i * 100; sid = support[i * 2 + 1]; deg = s_deg_r[i];      outp = g_svec + i * 256 + 128; }

    int t = threadIdx.x, lane = t & 31, w = t >> 5;
    if (t < 128) {
        s_self[t] = sym[(size_t)sid * 128 + t];
        s_bias[t] = gwb[t] + gb[t];
    }
    if (t >= 128 && t < 128 + MAXK) {
        int n = t - 128;
        int r = conn[2 * n];
        s_gw[n] = gate_w[(r == PADID) ? 0 : r];
    }
    __syncthreads();

    if (w == 0) {
        float ss = 0.f;
#pragma unroll
        for (int i = 0; i < 4; i++) { float v = s_self[lane + 32 * i]; ss += v * v; }
        for (int o = 16; o > 0; o >>= 1) ss += __shfl_xor_sync(~0u, ss, o);
        if (lane == 0) s_scal[0] = sqrtf(ss + EPS);
    }
    __syncthreads();
    float nself = s_scal[0];

    const float4* self4 = (const float4*)s_self;
    const float4* bias4 = (const float4*)s_bias;
    float4 sf = self4[lane];
    float4 bf = bias4[lane];

    for (int base = 0; base < 56; base += 8) {
        int n = base + w;
        if (n < MAXK) {
            int rel = conn[2 * n], ent = conn[2 * n + 1];
            float4 a = ((const float4*)(g_P + (size_t)rel * 256))[lane];
            float4 bb = ((const float4*)(g_P + (size_t)ent * 256 + 128))[lane];
            float va[4] = {a.x + bb.x + bf.x, a.y + bb.y + bf.y,
                           a.z + bb.z + bf.z, a.w + bb.w + bf.w};
            float sfv[4] = {sf.x, sf.y, sf.z, sf.w};
            float dp = 0.f, nn = 0.f;
            float4 pv;
#pragma unroll
            for (int i = 0; i < 4; i++) {
                float v = va[i];
                v = (v > 0.f) ? v : 0.01f * v;
                if (rel == PADID) v = 0.f;
                (&pv.x)[i] = v;
                dp += sfv[i] * v;
                nn += v * v;
            }
            ((float4*)s_proj[n])[lane] = pv;
            for (int o = 16; o > 0; o >>= 1) {
                dp += __shfl_xor_sync(~0u, dp, o);
                nn += __shfl_xor_sync(~0u, nn, o);
            }
            if (lane == 0) {
                float nnei = sqrtf(nn + EPS);
                s_cos[n] = dp / (nself * nnei + EPS);
            }
        }
    }
    __syncthreads();

    if (w == 0) {
        float v0 = s_cos[lane];
        float v1 = (lane + 32 < MAXK) ? s_cos[lane + 32] : -3.0e38f;
#pragma unroll
        for (int k = 0; k < KNEI; k++) {
            float bv = v0; int bi = lane;
            if (v1 > bv) { bv = v1; bi = lane + 32; }
            for (int o = 16; o > 0; o >>= 1) {
                float ov = __shfl_xor_sync(~0u, bv, o);
                int   oi = __shfl_xor_sync(~0u, bi, o);
                if (ov > bv || (ov == bv && oi < bi)) { bv = ov; bi = oi; }
            }
            if (lane == 0) s_sel[k] = bi;
            if (bi == lane) v0 = -3.0e38f;
            else if (bi == lane + 32) v1 = -3.0e38f;
        }
    } else if (w == 1) {
        float gv = s_gw[lane];
        gv += (lane + 32 < MAXK) ? s_gw[lane + 32] : 0.f;
        for (int o = 16; o > 0; o >>= 1) gv += __shfl_xor_sync(~0u, gv, o);
        if (lane == 0) {
            float gate = sigf((gv / 50.f) / gate_temp[0]);
            if (deg <= 0) gate = 1.f;
            s_scal[1] = gate;
        }
    }
    __syncthreads();

    if (t < 128) {
        float agg = 0.f;
#pragma unroll
        for (int k = 0; k < KNEI; k++) agg += s_proj[s_sel[k]][t];
        agg /= 10.f;
        outp[t] = tanhf(s_self[t] + s_scal[1] * agg);
    }
}

// ---------------------------------------------------------------------------
// Support encoder stages
// ---------------------------------------------------------------------------
__global__ void se1_kernel(const float* __restrict__ W1, const float* __restrict__ b1)
{
    int gw = (blockIdx.x * blockDim.x + threadIdx.x) >> 5;
    int lane = threadIdx.x & 31;
    if (gw >= FEW * 512) return;
    int r = gw >> 9, j = gw & 511;
    const float4* x = (const float4*)(g_svec + r * 256);
    const float4* w = (const float4*)(W1 + (size_t)j * 256);
    float acc = 0.f;
#pragma unroll
    for (int k = lane; k < 64; k += 32) {
        float4 xv = x[k], wv = w[k];
        acc = fmaf(xv.x, wv.x, acc); acc = fmaf(xv.y, wv.y, acc);
        acc = fmaf(xv.z, wv.z, acc); acc = fmaf(xv.w, wv.w, acc);
    }
    for (int o = 16; o > 0; o >>= 1) acc += __shfl_xor_sync(~0u, acc, o);
    if (lane == 0) g_sh1[r * 512 + j] = fmaxf(acc + b1[j], 0.f);
}

__global__ void se2_kernel(const float* __restrict__ W2, const float* __restrict__ b2)
{
    int gw = (blockIdx.x * blockDim.x + threadIdx.x) >> 5;
    int lane = threadIdx.x & 31;
    if (gw >= FEW * 256) return;
    int r = gw >> 8, c = gw & 255;
    const float4* x = (const float4*)(g_sh1 + r * 512);
    const float4* w = (const float4*)(W2 + (size_t)c * 512);
    float acc = 0.f;
#pragma unroll
    for (int k = lane; k < 128; k += 32) {
        float4 xv = x[k], wv = w[k];
        acc = fmaf(xv.x, wv.x, acc); acc = fmaf(xv.y, wv.y, acc);
        acc = fmaf(xv.z, wv.z, acc); acc = fmaf(xv.w, wv.w, acc);
    }
    for (int o = 16; o > 0; o >>= 1) acc += __shfl_xor_sync(~0u, acc, o);
    if (lane == 0) g_sh[r * 256 + c] = acc + b2[c] + g_svec[r * 256 + c];
}

__global__ void se3_kernel(const float* __restrict__ g, const float* __restrict__ b)
{
    __shared__ float smu[FEW], srs[FEW];
    __shared__ float red[8];
    int t = threadIdx.x, lane = t & 31, w = t >> 5;

    if (w < FEW) {
        const float* row = g_sh + w * 256;
        float s = 0.f;
#pragma unroll
        for (int i = 0; i < 8; i++) s += row[lane + 32 * i];
        for (int o = 16; o > 0; o >>= 1) s += __shfl_xor_sync(~0u, s, o);
        float mu = s / 256.f;
        float q = 0.f;
#pragma unroll
        for (int i = 0; i < 8; i++) { float d = row[lane + 32 * i] - mu; q += d * d; }
        for (int o = 16; o > 0; o >>= 1) q += __shfl_xor_sync(~0u, q, o);
        if (lane == 0) { smu[w] = mu; srs[w] = 1.f / sqrtf(q / 256.f + LNEPS); }
    }
    __syncthreads();

    float acc = 0.f;
#pragma unroll
    for (int r = 0; r < FEW; r++)
        acc += g[t] * (g_sh[r * 256 + t] - smu[r]) * srs[r] + b[t];
    acc *= 0.2f;
    g_sg[t] = acc;

    float nq = acc * acc;
    for (int o = 16; o > 0; o >>= 1) nq += __shfl_xor_sync(~0u, nq, o);
    if (lane == 0) red[w] = nq;
    __syncthreads();
    if (t == 0) {
        float s = 0.f;
        for (int i = 0; i < 8; i++) s += red[i];
        g_sgn[0] = sqrtf(s + EPS);
    }
}

// ---------------------------------------------------------------------------
// LSTM prep: interleaved packing, packed row j = 4*unit + gate.
// ---------------------------------------------------------------------------
__global__ void prep_lstm_kernel(const float* __restrict__ Wih, const float* __restrict__ Whh,
                                 const float* __restrict__ bih, const float* __restrict__ bhh)
{
    int j = blockIdx.x;
    int u = j >> 2, gidx = j & 3;
    int jm = gidx * 512 + u;
    int t = threadIdx.x;
    g_Wihp[j * 256 + t]  = Wih[jm * 256 + t];
    g_WhhLp[j * 256 + t] = Whh[jm * 512 + t];
    float p = g_sg[t] * Whh[jm * 512 + 256 + t];
    __shared__ float red[8];
    for (int o = 16; o > 0; o >>= 1) p += __shfl_xor_sync(~0u, p, o);
    if ((t & 31) == 0) red[t >> 5] = p;
    __syncthreads();
    if (t == 0) {
        float s = 0.f;
        for (int i = 0; i < 8; i++) s += red[i];
        g_whhr[j] = s;
        g_bsum[j] = bih[jm] + bhh[jm];
    }
}

// ---------------------------------------------------------------------------
// LayerNorm rows of g_tmp -> g_X
// ---------------------------------------------------------------------------
__global__ void ln_kernel(const float* __restrict__ g, const float* __restrict__ b)
{
    int row = blockIdx.x, t = threadIdx.x;
    float v = g_tmp[(size_t)row * 256 + t];
    __shared__ float red[8];
    __shared__ float s_mu, s_rs;
    float s = v;
    for (int o = 16; o > 0; o >>= 1) s += __shfl_xor_sync(~0u, s, o);
    if ((t & 31) == 0) red[t >> 5] = s;
    __syncthreads();
    if (t == 0) { float m = 0.f; for (int i = 0; i < 8; i++) m += red[i]; s_mu = m / 256.f; }
    __syncthreads();
    float d = v - s_mu;
    float q = d * d;
    for (int o = 16; o > 0; o >>= 1) q += __shfl_xor_sync(~0u, q, o);
    if ((t & 31) == 0) red[t >> 5] = q;
    __syncthreads();
    if (t == 0) { float m = 0.f; for (int i = 0; i < 8; i++) m += red[i]; s_rs = 1.f / sqrtf(m / 256.f + LNEPS); }
    __syncthreads();
    g_X[(size_t)row * 256 + t] = g[t] * d * s_rs + b[t];
}

// ---------------------------------------------------------------------------
// Final cosine vs support_g
// ---------------------------------------------------------------------------
__global__ void final_kernel(const float* __restrict__ h_in, float* __restrict__ out)
{
    __shared__ float ssg[256];
    int t = threadIdx.x, lane = t & 31, w = t >> 5;
    ssg[t] = g_sg[t];
    __syncthreads();
    int row = blockIdx.x * 8 + w;
    const float* h = h_in + (size_t)row * 256;
    float dp = 0.f, nq = 0.f;
#pragma unroll
    for (int i = 0; i < 8; i++) {
        int d = lane + 32 * i;
        float v = h[d];
        dp += v * ssg[d];
        nq += v * v;
    }
    for (int o = 16; o > 0; o >>= 1) {
        dp += __shfl_xor_sync(~0u, dp, o);
        nq += __shfl_xor_sync(~0u, nq, o);
    }
    if (lane == 0) out[row] = dp / (sqrtf(nq + EPS) * g_sgn[0]);
}

// ---------------------------------------------------------------------------
// kernel_launch
// ---------------------------------------------------------------------------
extern "C" void kernel_launch(void* const* d_in, const int* in_sizes, int n_in,
                              void* d_out, int out_size)
{
    const int*   query     = (const int*)d_in[0];
    const int*   support   = (const int*)d_in[1];
    const int*   q_l1      = (const int*)d_in[2];
    const int*   q_deg_l   = (const int*)d_in[3];
    const int*   q_r1      = (const int*)d_in[4];
    const int*   q_deg_r   = (const int*)d_in[5];
    const int*   s_l1      = (const int*)d_in[6];
    const int*   s_deg_l   = (const int*)d_in[7];
    const int*   s_r1      = (const int*)d_in[8];
    const int*   s_deg_r   = (const int*)d_in[9];
    const float* sym       = (const float*)d_in[10];
    const float* gcn_w_W   = (const float*)d_in[11];
    const float* gcn_w_b   = (const float*)d_in[12];
    const float* gcn_b     = (const float*)d_in[13];
    const float* gate_w    = (const float*)d_in[14];
    const float* gate_temp = (const float*)d_in[15];
    const float* se_W1     = (const float*)d_in[16];
    const float* se_b1     = (const float*)d_in[17];
    const float* se_W2     = (const float*)d_in[18];
    const float* se_b2     = (const float*)d_in[19];
    const float* ln_g      = (const float*)d_in[20];
    const float* ln_b      = (const float*)d_in[21];
    const float* lstm_Wih  = (const float*)d_in[22];
    const float* lstm_Whh  = (const float*)d_in[23];
    const float* lstm_bih  = (const float*)d_in[24];
    const float* lstm_bhh  = (const float*)d_in[25];
    float* out = (float*)d_out;

    float *pP, *pWt, *pQv, *pH1, *pTmp, *pX, *pWihp, *pWhhLp, *pBsum, *pWhhr, *pGq, *pH, *pH2;
    cudaGetSymbolAddress((void**)&pP,     g_P);
    cudaGetSymbolAddress((void**)&pWt,    g_Wt);
    cudaGetSymbolAddress((void**)&pQv,    g_qvec);
    cudaGetSymbolAddress((void**)&pH1,    g_H1);
    cudaGetSymbolAddress((void**)&pTmp,   g_tmp);
    cudaGetSymbolAddress((void**)&pX,     g_X);
    cudaGetSymbolAddress((void**)&pWihp,  g_Wihp);
    cudaGetSymbolAddress((void**)&pWhhLp, g_WhhLp);
    cudaGetSymbolAddress((void**)&pBsum,  g_bsum);
    cudaGetSymbolAddress((void**)&pWhhr,  g_whhr);
    cudaGetSymbolAddress((void**)&pGq,    g_Gq);
    cudaGetSymbolAddress((void**)&pH,     g_h);
    cudaGetSymbolAddress((void**)&pH2,    g_h2);

    const int SM_T = 2 * 128 * SMS * (int)sizeof(float);
    const int SM_B = 4 * 128 * BSMS * (int)sizeof(uint32_t);
    static int attr_done = 0;
    if (!attr_done) {
        cudaFuncSetAttribute(tgemm_kernel<0>, cudaFuncAttributeMaxDynamicSharedMemorySize, SM_T);
        cudaFuncSetAttribute(tgemm_kernel<1>, cudaFuncAttributeMaxDynamicSharedMemorySize, SM_T);
        cudaFuncSetAttribute(tgemm_kernel<2>, cudaFuncAttributeMaxDynamicSharedMemorySize, SM_T);
        cudaFuncSetAttribute(bgemm_kernel,    cudaFuncAttributeMaxDynamicSharedMemorySize, SM_B);
        attr_done = 1;
    }

    // 1) P = sym_emb @ Wt^T  (bf16x3)
    pack_wt_kernel<<<256, 128>>>(gcn_w_W);
    bgemm_kernel<<<dim3(2, (NSYM + 1 + 127) / 128), 256, SM_B>>>(
        sym, 128, pWt, 128, pP, 256, NSYM + 1, 256, 128);

    // 2) neighbor encoder -> g_qvec, g_svec
    neighbor_kernel<<<8202, 256>>>(query, support, q_l1, q_deg_l, q_r1, q_deg_r,
                                   s_l1, s_deg_l, s_r1, s_deg_r,
                                   sym, gcn_w_b, gcn_b, gate_w, gate_temp);

    // 3) support encoder -> g_sg, g_sgn
    se1_kernel<<<(FEW * 512 + 7) / 8, 256>>>(se_W1, se_b1);
    se2_kernel<<<(FEW * 256 + 7) / 8, 256>>>(se_W2, se_b2);
    se3_kernel<<<1, 256>>>(ln_g, ln_b);

    // 4) LSTM weight packing (interleaved) + constants
    prep_lstm_kernel<<<1024, 256>>>(lstm_Wih, lstm_Whh, lstm_bih, lstm_bhh);

    // 5) query support-encoder + LN  (tf32)
    tgemm_kernel<0><<<dim3(4, 32), 256, SM_T>>>(pQv, 256, se_W1, 256, pH1, 512,
                                                B, 512, 256, se_b1, nullptr, 0, 1, nullptr);
    tgemm_kernel<0><<<dim3(2, 32), 256, SM_T>>>(pH1, 512, se_W2, 512, pTmp, 256,
                                                B, 256, 512, se_b2, pQv, 256, 0, nullptr);
    ln_kernel<<<B, 256>>>(ln_g, ln_b);

    // 6) Gq = X @ Wihp^T + bsum; fused LSTM step 1 -> h in g_h
    tgemm_kernel<1><<<dim3(8, 32), 256, SM_T>>>(pX, 256, pWihp, 256, pGq, 1024,
                                                B, 1024, 256, pBsum, nullptr, 0, 0, pH);

    // 7) LSTM steps 2..4 (fused elementwise, double-buffered h)
    tgemm_kernel<2><<<dim3(8, 32), 256, SM_T>>>(pH, 256, pWhhLp, 256, nullptr, 0,
                                                B, 1024, 256, pWhhr, pGq, 1024, 0, pH2);
    tgemm_kernel<2><<<dim3(8, 32), 256, SM_T>>>(pH2, 256, pWhhLp, 256, nullptr, 0,
                                                B, 1024, 256, pWhhr, pGq, 1024, 0, pH);
    tgemm_kernel<2><<<dim3(8, 32), 256, SM_T>>>(pH, 256, pWhhLp, 256, nullptr, 0,
                                                B, 1024, 256, pWhhr, pGq, 1024, 0, pH2);

    // 8) final cosine
    final_kernel<<<B / 8, 256>>>(pH2, out);
}